// round 1
// baseline (speedup 1.0000x reference)
#include <cuda_runtime.h>
#include <math.h>

#define DIMV   1536
#define NH     24
#define HD     64
#define SEQ    4096
#define BATCH  4
#define NT     (BATCH*SEQ)   // 16384 tokens
#define N3     (3*DIMV)      // 4608

// Scratch (static __device__ arrays: allowed by harness rules)
__device__ float g_qkv[(size_t)NT * N3];     // raw projection output
__device__ float g_q[(size_t)NT * DIMV];     // [bh][s][d]
__device__ float g_k[(size_t)NT * DIMV];
__device__ float g_v[(size_t)NT * DIMV];

// ---------------------------------------------------------------------------
// Kernel A: qkv = x @ w + b     (M=16384, N=4608, K=1536)
// 128x128 tile, BK=16, 256 threads, 8x8 per thread
// ---------------------------------------------------------------------------
__global__ __launch_bounds__(256) void qkv_gemm(const float* __restrict__ X,
                                                const float* __restrict__ W,
                                                const float* __restrict__ bias) {
    __shared__ float As[16 * 128];   // [k][m]
    __shared__ float Bs[16 * 128];   // [k][n]

    const int tid = threadIdx.x;
    const int m0 = blockIdx.y * 128;
    const int n0 = blockIdx.x * 128;
    const int ty = tid >> 4;         // 0..15
    const int tx = tid & 15;         // 0..15

    float acc[8][8];
#pragma unroll
    for (int i = 0; i < 8; i++)
#pragma unroll
        for (int j = 0; j < 8; j++) acc[i][j] = 0.f;

    const int ar = tid >> 1;             // 0..127 (A row within tile)
    const int ac = (tid & 1) * 2;        // float4 col group 0 or 2

    for (int k0 = 0; k0 < DIMV; k0 += 16) {
        // Load A tile (transposed store: As[k][m])
#pragma unroll
        for (int u = 0; u < 2; u++) {
            const int col4 = ac + u;     // 0..3
            float4 v = *(const float4*)&X[(size_t)(m0 + ar) * DIMV + k0 + col4 * 4];
            As[(col4 * 4 + 0) * 128 + ar] = v.x;
            As[(col4 * 4 + 1) * 128 + ar] = v.y;
            As[(col4 * 4 + 2) * 128 + ar] = v.z;
            As[(col4 * 4 + 3) * 128 + ar] = v.w;
        }
        // Load B tile (natural store: Bs[k][n])
#pragma unroll
        for (int u = 0; u < 2; u++) {
            const int i = tid + u * 256;       // 0..511
            const int row = i >> 5;            // 0..15
            const int col4 = i & 31;           // 0..31
            *(float4*)&Bs[row * 128 + col4 * 4] =
                *(const float4*)&W[(size_t)(k0 + row) * N3 + n0 + col4 * 4];
        }
        __syncthreads();

#pragma unroll
        for (int kk = 0; kk < 16; kk++) {
            float a[8], b[8];
            *(float4*)&a[0] = *(float4*)&As[kk * 128 + ty * 8];
            *(float4*)&a[4] = *(float4*)&As[kk * 128 + ty * 8 + 4];
            *(float4*)&b[0] = *(float4*)&Bs[kk * 128 + tx * 8];
            *(float4*)&b[4] = *(float4*)&Bs[kk * 128 + tx * 8 + 4];
#pragma unroll
            for (int i = 0; i < 8; i++)
#pragma unroll
                for (int j = 0; j < 8; j++)
                    acc[i][j] += a[i] * b[j];
        }
        __syncthreads();
    }

    // Epilogue: add bias, store
    float bv[8];
#pragma unroll
    for (int j = 0; j < 8; j++) bv[j] = bias[n0 + tx * 8 + j];

#pragma unroll
    for (int i = 0; i < 8; i++) {
        const size_t row = (size_t)(m0 + ty * 8 + i);
        float4 o0 = make_float4(acc[i][0] + bv[0], acc[i][1] + bv[1],
                                acc[i][2] + bv[2], acc[i][3] + bv[3]);
        float4 o1 = make_float4(acc[i][4] + bv[4], acc[i][5] + bv[5],
                                acc[i][6] + bv[6], acc[i][7] + bv[7]);
        *(float4*)&g_qkv[row * N3 + n0 + tx * 8]     = o0;
        *(float4*)&g_qkv[row * N3 + n0 + tx * 8 + 4] = o1;
    }
}

// ---------------------------------------------------------------------------
// Kernel B: per (token, head): RMSNorm(q), RMSNorm(k), RoPE(q), RoPE(k),
// transpose q/k/v into [bh][s][d] layout.  One warp per (token, head).
// ---------------------------------------------------------------------------
__global__ __launch_bounds__(256) void norm_rope(const float* __restrict__ cosb,
                                                 const float* __restrict__ sinb) {
    const int w = blockIdx.x * 8 + (threadIdx.x >> 5);   // global warp id
    const int lane = threadIdx.x & 31;
    const int t = w / NH;            // token 0..16383
    const int h = w - t * NH;        // head
    const int b = t >> 12;           // /4096
    const int s = t & (SEQ - 1);

    const float* base = g_qkv + (size_t)t * N3 + h * HD;
    float2 q = *(const float2*)(base + 2 * lane);
    float2 k = *(const float2*)(base + DIMV + 2 * lane);
    float2 v = *(const float2*)(base + 2 * DIMV + 2 * lane);

    float sq = q.x * q.x + q.y * q.y;
    float sk = k.x * k.x + k.y * k.y;
#pragma unroll
    for (int o = 16; o >= 1; o >>= 1) {
        sq += __shfl_xor_sync(0xffffffffu, sq, o);
        sk += __shfl_xor_sync(0xffffffffu, sk, o);
    }
    const float rq = rsqrtf(sq * (1.0f / 64.0f) + 1e-6f);
    const float rk = rsqrtf(sk * (1.0f / 64.0f) + 1e-6f);

    const float c  = cosb[s * HD + 2 * lane];   // repeated pairs: [2i]==[2i+1]
    const float sn = sinb[s * HD + 2 * lane];

    const float qx = q.x * rq, qy = q.y * rq;
    const float kx = k.x * rk, ky = k.y * rk;
    float2 qo = make_float2(qx * c - qy * sn, qy * c + qx * sn);
    float2 ko = make_float2(kx * c - ky * sn, ky * c + kx * sn);

    const size_t o = ((size_t)(b * NH + h) * SEQ + s) * HD + 2 * lane;
    *(float2*)(g_q + o) = qo;
    *(float2*)(g_k + o) = ko;
    *(float2*)(g_v + o) = v;
}

// ---------------------------------------------------------------------------
// Kernel C: flash attention, fp32.  Block = 64 q-rows of one (b,h).
// 256 threads, each owns a 4x4 micro-tile of S / O.
// ---------------------------------------------------------------------------
__global__ __launch_bounds__(256) void attn(float* __restrict__ out) {
    __shared__ float Qs[64 * 64];   // [d][m]
    __shared__ float Ks[64 * 64];   // [d][n], later reused as P[n][m]
    __shared__ float Vs[64 * 64];   // [n][d]

    const int tid = threadIdx.x;
    const int ty = tid >> 4;        // 0..15 (rows)
    const int tx = tid & 15;        // 0..15 (cols)
    const int bh = blockIdx.y;
    const int b = bh / NH;
    const int h = bh - b * NH;
    const int q0 = blockIdx.x * 64;

    const float* Qg = g_q + ((size_t)bh * SEQ + q0) * HD;
    const float* Kg = g_k + (size_t)bh * SEQ * HD;
    const float* Vg = g_v + (size_t)bh * SEQ * HD;

    // Load Q tile transposed: Qs[d][m]
#pragma unroll
    for (int u = 0; u < 4; u++) {
        const int i = tid + u * 256;      // 0..1023
        const int row = i >> 4;           // 0..63
        const int d4 = i & 15;            // 0..15
        float4 v = *(const float4*)&Qg[row * HD + d4 * 4];
        Qs[(d4 * 4 + 0) * 64 + row] = v.x;
        Qs[(d4 * 4 + 1) * 64 + row] = v.y;
        Qs[(d4 * 4 + 2) * 64 + row] = v.z;
        Qs[(d4 * 4 + 3) * 64 + row] = v.w;
    }

    float acc[4][4];
    float mrow[4], lrow[4];
#pragma unroll
    for (int i = 0; i < 4; i++) {
        mrow[i] = -INFINITY;
        lrow[i] = 0.f;
#pragma unroll
        for (int j = 0; j < 4; j++) acc[i][j] = 0.f;
    }

    const float scale = 0.125f;   // 1/sqrt(64)

    for (int kt = 0; kt < SEQ / 64; kt++) {
        const float* Kt = Kg + (size_t)kt * 64 * HD;
        const float* Vt = Vg + (size_t)kt * 64 * HD;
        // Load K transposed, V natural
#pragma unroll
        for (int u = 0; u < 4; u++) {
            const int i = tid + u * 256;
            const int row = i >> 4;
            const int d4 = i & 15;
            float4 kv = *(const float4*)&Kt[row * HD + d4 * 4];
            Ks[(d4 * 4 + 0) * 64 + row] = kv.x;
            Ks[(d4 * 4 + 1) * 64 + row] = kv.y;
            Ks[(d4 * 4 + 2) * 64 + row] = kv.z;
            Ks[(d4 * 4 + 3) * 64 + row] = kv.w;
            *(float4*)&Vs[row * 64 + d4 * 4] = *(const float4*)&Vt[row * HD + d4 * 4];
        }
        __syncthreads();

        // S = Q K^T (this thread: rows ty*4.., cols tx*4..)
        float s[4][4];
#pragma unroll
        for (int i = 0; i < 4; i++)
#pragma unroll
            for (int j = 0; j < 4; j++) s[i][j] = 0.f;

#pragma unroll 16
        for (int d = 0; d < 64; d++) {
            float4 qv = *(float4*)&Qs[d * 64 + ty * 4];
            float4 kv = *(float4*)&Ks[d * 64 + tx * 4];
            const float qa[4] = {qv.x, qv.y, qv.z, qv.w};
            const float ka[4] = {kv.x, kv.y, kv.z, kv.w};
#pragma unroll
            for (int i = 0; i < 4; i++)
#pragma unroll
                for (int j = 0; j < 4; j++)
                    s[i][j] += qa[i] * ka[j];
        }
        __syncthreads();   // everyone done reading Ks

        // Online softmax (row group = 16 lanes sharing ty)
#pragma unroll
        for (int i = 0; i < 4; i++) {
            float mi = fmaxf(fmaxf(s[i][0], s[i][1]), fmaxf(s[i][2], s[i][3])) * scale;
#pragma unroll
            for (int o = 8; o >= 1; o >>= 1)
                mi = fmaxf(mi, __shfl_xor_sync(0xffffffffu, mi, o));
            const float mnew = fmaxf(mrow[i], mi);
            const float alpha = __expf(mrow[i] - mnew);
            mrow[i] = mnew;
            float rs = 0.f;
#pragma unroll
            for (int j = 0; j < 4; j++) {
                s[i][j] = __expf(s[i][j] * scale - mnew);
                rs += s[i][j];
            }
#pragma unroll
            for (int o = 8; o >= 1; o >>= 1)
                rs += __shfl_xor_sync(0xffffffffu, rs, o);
            lrow[i] = lrow[i] * alpha + rs;
#pragma unroll
            for (int j = 0; j < 4; j++) acc[i][j] *= alpha;
        }

        // Store P transposed into Ks region: P[n][m]
#pragma unroll
        for (int j = 0; j < 4; j++) {
            float4 pv = make_float4(s[0][j], s[1][j], s[2][j], s[3][j]);
            *(float4*)&Ks[(tx * 4 + j) * 64 + ty * 4] = pv;
        }
        __syncthreads();

        // O += P V  (this thread: rows ty*4.., d cols tx*4..)
#pragma unroll 16
        for (int n = 0; n < 64; n++) {
            float4 pv = *(float4*)&Ks[n * 64 + ty * 4];
            float4 vv = *(float4*)&Vs[n * 64 + tx * 4];
            const float pa[4] = {pv.x, pv.y, pv.z, pv.w};
            const float va[4] = {vv.x, vv.y, vv.z, vv.w};
#pragma unroll
            for (int i = 0; i < 4; i++)
#pragma unroll
                for (int j = 0; j < 4; j++)
                    acc[i][j] += pa[i] * va[j];
        }
        __syncthreads();
    }

    // Normalize and write: out[b][s][h*64 + d]
#pragma unroll
    for (int i = 0; i < 4; i++) {
        const float inv = 1.0f / lrow[i];
        const int sg = q0 + ty * 4 + i;
        float4 o = make_float4(acc[i][0] * inv, acc[i][1] * inv,
                               acc[i][2] * inv, acc[i][3] * inv);
        *(float4*)&out[((size_t)b * SEQ + sg) * DIMV + h * HD + tx * 4] = o;
    }
}

// ---------------------------------------------------------------------------
extern "C" void kernel_launch(void* const* d_in, const int* in_sizes, int n_in,
                              void* d_out, int out_size) {
    const float* x    = (const float*)d_in[0];   // (4,4096,1536)
    const float* cosb = (const float*)d_in[1];   // (4096,64)
    const float* sinb = (const float*)d_in[2];   // (4096,64)
    const float* w    = (const float*)d_in[3];   // (1536,4608)
    const float* bq   = (const float*)d_in[4];   // (4608,)

    qkv_gemm<<<dim3(N3 / 128, NT / 128), 256>>>(x, w, bq);
    norm_rope<<<dim3((NT * NH) / 8), 256>>>(cosb, sinb);
    attn<<<dim3(SEQ / 64, BATCH * NH), 256>>>((float*)d_out);
}

// round 2
// speedup vs baseline: 1.0000x; 1.0000x over previous
#include <cuda_runtime.h>
#include <math.h>

#define DIMV   1536
#define NH     24
#define HD     64
#define SEQ    4096
#define BATCH  4
#define NT     (BATCH*SEQ)   // 16384 tokens
#define N3     (3*DIMV)      // 4608

// Scratch (static __device__ arrays: allowed by harness rules)
__device__ float g_qkv[(size_t)NT * N3];     // raw projection output
__device__ float g_q[(size_t)NT * DIMV];     // [bh][s][d]
__device__ float g_k[(size_t)NT * DIMV];
__device__ float g_v[(size_t)NT * DIMV];

// ---------------------------------------------------------------------------
// Kernel A: qkv = x @ w + b     (M=16384, N=4608, K=1536)
// 128x128 tile, BK=16, 256 threads, 8x8 per thread
// ---------------------------------------------------------------------------
__global__ __launch_bounds__(256) void qkv_gemm(const float* __restrict__ X,
                                                const float* __restrict__ W,
                                                const float* __restrict__ bias) {
    __shared__ float As[16 * 128];   // [k][m]
    __shared__ float Bs[16 * 128];   // [k][n]

    const int tid = threadIdx.x;
    const int m0 = blockIdx.y * 128;
    const int n0 = blockIdx.x * 128;
    const int ty = tid >> 4;         // 0..15
    const int tx = tid & 15;         // 0..15

    float acc[8][8];
#pragma unroll
    for (int i = 0; i < 8; i++)
#pragma unroll
        for (int j = 0; j < 8; j++) acc[i][j] = 0.f;

    const int ar = tid >> 1;             // 0..127 (A row within tile)
    const int ac = (tid & 1) * 2;        // float4 col group 0 or 2

    for (int k0 = 0; k0 < DIMV; k0 += 16) {
        // Load A tile (transposed store: As[k][m])
#pragma unroll
        for (int u = 0; u < 2; u++) {
            const int col4 = ac + u;     // 0..3
            float4 v = *(const float4*)&X[(size_t)(m0 + ar) * DIMV + k0 + col4 * 4];
            As[(col4 * 4 + 0) * 128 + ar] = v.x;
            As[(col4 * 4 + 1) * 128 + ar] = v.y;
            As[(col4 * 4 + 2) * 128 + ar] = v.z;
            As[(col4 * 4 + 3) * 128 + ar] = v.w;
        }
        // Load B tile (natural store: Bs[k][n])
#pragma unroll
        for (int u = 0; u < 2; u++) {
            const int i = tid + u * 256;       // 0..511
            const int row = i >> 5;            // 0..15
            const int col4 = i & 31;           // 0..31
            *(float4*)&Bs[row * 128 + col4 * 4] =
                *(const float4*)&W[(size_t)(k0 + row) * N3 + n0 + col4 * 4];
        }
        __syncthreads();

#pragma unroll
        for (int kk = 0; kk < 16; kk++) {
            float a[8], b[8];
            *(float4*)&a[0] = *(float4*)&As[kk * 128 + ty * 8];
            *(float4*)&a[4] = *(float4*)&As[kk * 128 + ty * 8 + 4];
            *(float4*)&b[0] = *(float4*)&Bs[kk * 128 + tx * 8];
            *(float4*)&b[4] = *(float4*)&Bs[kk * 128 + tx * 8 + 4];
#pragma unroll
            for (int i = 0; i < 8; i++)
#pragma unroll
                for (int j = 0; j < 8; j++)
                    acc[i][j] += a[i] * b[j];
        }
        __syncthreads();
    }

    // Epilogue: add bias, store
    float bv[8];
#pragma unroll
    for (int j = 0; j < 8; j++) bv[j] = bias[n0 + tx * 8 + j];

#pragma unroll
    for (int i = 0; i < 8; i++) {
        const size_t row = (size_t)(m0 + ty * 8 + i);
        float4 o0 = make_float4(acc[i][0] + bv[0], acc[i][1] + bv[1],
                                acc[i][2] + bv[2], acc[i][3] + bv[3]);
        float4 o1 = make_float4(acc[i][4] + bv[4], acc[i][5] + bv[5],
                                acc[i][6] + bv[6], acc[i][7] + bv[7]);
        *(float4*)&g_qkv[row * N3 + n0 + tx * 8]     = o0;
        *(float4*)&g_qkv[row * N3 + n0 + tx * 8 + 4] = o1;
    }
}

// ---------------------------------------------------------------------------
// Kernel B: per (token, head): RMSNorm(q), RMSNorm(k), RoPE(q), RoPE(k),
// transpose q/k/v into [bh][s][d] layout.  One warp per (token, head).
// ---------------------------------------------------------------------------
__global__ __launch_bounds__(256) void norm_rope(const float* __restrict__ cosb,
                                                 const float* __restrict__ sinb) {
    const int w = blockIdx.x * 8 + (threadIdx.x >> 5);   // global warp id
    const int lane = threadIdx.x & 31;
    const int t = w / NH;            // token 0..16383
    const int h = w - t * NH;        // head
    const int b = t >> 12;           // /4096
    const int s = t & (SEQ - 1);

    const float* base = g_qkv + (size_t)t * N3 + h * HD;
    float2 q = *(const float2*)(base + 2 * lane);
    float2 k = *(const float2*)(base + DIMV + 2 * lane);
    float2 v = *(const float2*)(base + 2 * DIMV + 2 * lane);

    float sq = q.x * q.x + q.y * q.y;
    float sk = k.x * k.x + k.y * k.y;
#pragma unroll
    for (int o = 16; o >= 1; o >>= 1) {
        sq += __shfl_xor_sync(0xffffffffu, sq, o);
        sk += __shfl_xor_sync(0xffffffffu, sk, o);
    }
    const float rq = rsqrtf(sq * (1.0f / 64.0f) + 1e-6f);
    const float rk = rsqrtf(sk * (1.0f / 64.0f) + 1e-6f);

    const float c  = cosb[s * HD + 2 * lane];   // repeated pairs: [2i]==[2i+1]
    const float sn = sinb[s * HD + 2 * lane];

    const float qx = q.x * rq, qy = q.y * rq;
    const float kx = k.x * rk, ky = k.y * rk;
    float2 qo = make_float2(qx * c - qy * sn, qy * c + qx * sn);
    float2 ko = make_float2(kx * c - ky * sn, ky * c + kx * sn);

    const size_t o = ((size_t)(b * NH + h) * SEQ + s) * HD + 2 * lane;
    *(float2*)(g_q + o) = qo;
    *(float2*)(g_k + o) = ko;
    *(float2*)(g_v + o) = v;
}

// ---------------------------------------------------------------------------
// Kernel C: flash attention, fp32.  Block = 64 q-rows of one (b,h).
// 256 threads, each owns a 4x4 micro-tile of S / O.
// ---------------------------------------------------------------------------
__global__ __launch_bounds__(256) void attn(float* __restrict__ out) {
    __shared__ float Qs[64 * 64];   // [d][m]
    __shared__ float Ks[64 * 64];   // [d][n], later reused as P[n][m]
    __shared__ float Vs[64 * 64];   // [n][d]

    const int tid = threadIdx.x;
    const int ty = tid >> 4;        // 0..15 (rows)
    const int tx = tid & 15;        // 0..15 (cols)
    const int bh = blockIdx.y;
    const int b = bh / NH;
    const int h = bh - b * NH;
    const int q0 = blockIdx.x * 64;

    const float* Qg = g_q + ((size_t)bh * SEQ + q0) * HD;
    const float* Kg = g_k + (size_t)bh * SEQ * HD;
    const float* Vg = g_v + (size_t)bh * SEQ * HD;

    // Load Q tile transposed: Qs[d][m]
#pragma unroll
    for (int u = 0; u < 4; u++) {
        const int i = tid + u * 256;      // 0..1023
        const int row = i >> 4;           // 0..63
        const int d4 = i & 15;            // 0..15
        float4 v = *(const float4*)&Qg[row * HD + d4 * 4];
        Qs[(d4 * 4 + 0) * 64 + row] = v.x;
        Qs[(d4 * 4 + 1) * 64 + row] = v.y;
        Qs[(d4 * 4 + 2) * 64 + row] = v.z;
        Qs[(d4 * 4 + 3) * 64 + row] = v.w;
    }

    float acc[4][4];
    float mrow[4], lrow[4];
#pragma unroll
    for (int i = 0; i < 4; i++) {
        mrow[i] = -INFINITY;
        lrow[i] = 0.f;
#pragma unroll
        for (int j = 0; j < 4; j++) acc[i][j] = 0.f;
    }

    const float scale = 0.125f;   // 1/sqrt(64)

    for (int kt = 0; kt < SEQ / 64; kt++) {
        const float* Kt = Kg + (size_t)kt * 64 * HD;
        const float* Vt = Vg + (size_t)kt * 64 * HD;
        // Load K transposed, V natural
#pragma unroll
        for (int u = 0; u < 4; u++) {
            const int i = tid + u * 256;
            const int row = i >> 4;
            const int d4 = i & 15;
            float4 kv = *(const float4*)&Kt[row * HD + d4 * 4];
            Ks[(d4 * 4 + 0) * 64 + row] = kv.x;
            Ks[(d4 * 4 + 1) * 64 + row] = kv.y;
            Ks[(d4 * 4 + 2) * 64 + row] = kv.z;
            Ks[(d4 * 4 + 3) * 64 + row] = kv.w;
            *(float4*)&Vs[row * 64 + d4 * 4] = *(const float4*)&Vt[row * HD + d4 * 4];
        }
        __syncthreads();

        // S = Q K^T (this thread: rows ty*4.., cols tx*4..)
        float s[4][4];
#pragma unroll
        for (int i = 0; i < 4; i++)
#pragma unroll
            for (int j = 0; j < 4; j++) s[i][j] = 0.f;

#pragma unroll 16
        for (int d = 0; d < 64; d++) {
            float4 qv = *(float4*)&Qs[d * 64 + ty * 4];
            float4 kv = *(float4*)&Ks[d * 64 + tx * 4];
            const float qa[4] = {qv.x, qv.y, qv.z, qv.w};
            const float ka[4] = {kv.x, kv.y, kv.z, kv.w};
#pragma unroll
            for (int i = 0; i < 4; i++)
#pragma unroll
                for (int j = 0; j < 4; j++)
                    s[i][j] += qa[i] * ka[j];
        }
        __syncthreads();   // everyone done reading Ks

        // Online softmax (row group = 16 lanes sharing ty)
#pragma unroll
        for (int i = 0; i < 4; i++) {
            float mi = fmaxf(fmaxf(s[i][0], s[i][1]), fmaxf(s[i][2], s[i][3])) * scale;
#pragma unroll
            for (int o = 8; o >= 1; o >>= 1)
                mi = fmaxf(mi, __shfl_xor_sync(0xffffffffu, mi, o));
            const float mnew = fmaxf(mrow[i], mi);
            const float alpha = __expf(mrow[i] - mnew);
            mrow[i] = mnew;
            float rs = 0.f;
#pragma unroll
            for (int j = 0; j < 4; j++) {
                s[i][j] = __expf(s[i][j] * scale - mnew);
                rs += s[i][j];
            }
#pragma unroll
            for (int o = 8; o >= 1; o >>= 1)
                rs += __shfl_xor_sync(0xffffffffu, rs, o);
            lrow[i] = lrow[i] * alpha + rs;
#pragma unroll
            for (int j = 0; j < 4; j++) acc[i][j] *= alpha;
        }

        // Store P transposed into Ks region: P[n][m]
#pragma unroll
        for (int j = 0; j < 4; j++) {
            float4 pv = make_float4(s[0][j], s[1][j], s[2][j], s[3][j]);
            *(float4*)&Ks[(tx * 4 + j) * 64 + ty * 4] = pv;
        }
        __syncthreads();

        // O += P V  (this thread: rows ty*4.., d cols tx*4..)
#pragma unroll 16
        for (int n = 0; n < 64; n++) {
            float4 pv = *(float4*)&Ks[n * 64 + ty * 4];
            float4 vv = *(float4*)&Vs[n * 64 + tx * 4];
            const float pa[4] = {pv.x, pv.y, pv.z, pv.w};
            const float va[4] = {vv.x, vv.y, vv.z, vv.w};
#pragma unroll
            for (int i = 0; i < 4; i++)
#pragma unroll
                for (int j = 0; j < 4; j++)
                    acc[i][j] += pa[i] * va[j];
        }
        __syncthreads();
    }

    // Normalize and write: out[b][s][h*64 + d]
#pragma unroll
    for (int i = 0; i < 4; i++) {
        const float inv = 1.0f / lrow[i];
        const int sg = q0 + ty * 4 + i;
        float4 o = make_float4(acc[i][0] * inv, acc[i][1] * inv,
                               acc[i][2] * inv, acc[i][3] * inv);
        *(float4*)&out[((size_t)b * SEQ + sg) * DIMV + h * HD + tx * 4] = o;
    }
}

// ---------------------------------------------------------------------------
extern "C" void kernel_launch(void* const* d_in, const int* in_sizes, int n_in,
                              void* d_out, int out_size) {
    const float* x    = (const float*)d_in[0];   // (4,4096,1536)
    const float* cosb = (const float*)d_in[1];   // (4096,64)
    const float* sinb = (const float*)d_in[2];   // (4096,64)
    const float* w    = (const float*)d_in[3];   // (1536,4608)
    const float* bq   = (const float*)d_in[4];   // (4608,)

    qkv_gemm<<<dim3(N3 / 128, NT / 128), 256>>>(x, w, bq);
    norm_rope<<<dim3((NT * NH) / 8), 256>>>(cosb, sinb);
    attn<<<dim3(SEQ / 64, BATCH * NH), 256>>>((float*)d_out);
}

// round 4
// speedup vs baseline: 2.7529x; 2.7529x over previous
#include <cuda_runtime.h>
#include <cuda_bf16.h>
#include <math.h>
#include <stdint.h>

#define SEQ   4096
#define BATCH 4
#define NH    24
#define HD    64
#define DIMV  1536
#define N3    4608
#define NT    16384
#define BHN   96

__device__ __align__(16) unsigned short g_WThi[(size_t)N3 * DIMV];   // [n][k]
__device__ __align__(16) unsigned short g_WTlo[(size_t)N3 * DIMV];
__device__ __align__(16) unsigned short g_Qhi[(size_t)BHN * SEQ * HD]; // [bh][s][d]
__device__ __align__(16) unsigned short g_Qlo[(size_t)BHN * SEQ * HD];
__device__ __align__(16) unsigned short g_Khi[(size_t)BHN * SEQ * HD];
__device__ __align__(16) unsigned short g_Klo[(size_t)BHN * SEQ * HD];
__device__ __align__(16) unsigned short g_Vhi[(size_t)BHN * HD * SEQ]; // [bh][d][s]
__device__ __align__(16) unsigned short g_Vlo[(size_t)BHN * HD * SEQ];

// ---------------- helpers ----------------
__device__ __forceinline__ void mma16816(float* c, uint32_t a0, uint32_t a1,
                                         uint32_t a2, uint32_t a3,
                                         uint32_t b0, uint32_t b1) {
    asm volatile(
        "mma.sync.aligned.m16n8k16.row.col.f32.bf16.bf16.f32 "
        "{%0,%1,%2,%3},{%4,%5,%6,%7},{%8,%9},{%0,%1,%2,%3};"
        : "+f"(c[0]), "+f"(c[1]), "+f"(c[2]), "+f"(c[3])
        : "r"(a0), "r"(a1), "r"(a2), "r"(a3), "r"(b0), "r"(b1));
}

__device__ __forceinline__ void split2(float a, float b, uint32_t& hi, uint32_t& lo) {
    __nv_bfloat16 ha = __float2bfloat16_rn(a), hb = __float2bfloat16_rn(b);
    __nv_bfloat16 la = __float2bfloat16_rn(a - __bfloat162float(ha));
    __nv_bfloat16 lb = __float2bfloat16_rn(b - __bfloat162float(hb));
    hi = ((uint32_t)__bfloat16_as_ushort(hb) << 16) | (uint32_t)__bfloat16_as_ushort(ha);
    lo = ((uint32_t)__bfloat16_as_ushort(lb) << 16) | (uint32_t)__bfloat16_as_ushort(la);
}

// FMA-pipe exp2 (no MUFU). |y| <= 12 in our use.
__device__ __forceinline__ float exp2p(float y) {
    float r = y + 12582912.0f;            // 1.5*2^23 round-to-int magic
    float nf = r - 12582912.0f;
    float f = y - nf;                     // [-0.5, 0.5]
    int n = __float_as_int(r) - 0x4B400000;
    float p = 0.00133335581f;
    p = fmaf(p, f, 0.00961812910f);
    p = fmaf(p, f, 0.0555041087f);
    p = fmaf(p, f, 0.240226507f);
    p = fmaf(p, f, 0.693147182f);
    p = fmaf(p, f, 1.0f);
    return p * __int_as_float((n + 127) << 23);
}

__device__ __forceinline__ void st8(char* p, uint4 v) {   // 16 bytes via 2x 8B (stride-72/40 rows are 8B-aligned)
    *(uint2*)p = make_uint2(v.x, v.y);
    *(uint2*)(p + 8) = make_uint2(v.z, v.w);
}

// ---------------- Kernel 0: W transpose + bf16 hi/lo split ----------------
__global__ __launch_bounds__(256) void wt_prep(const float* __restrict__ W) {
    __shared__ float tile[32][33];
    const int n0 = blockIdx.x * 32, k0 = blockIdx.y * 32;
    const int tx = threadIdx.x & 31, ty = threadIdx.x >> 5;
    for (int r = ty; r < 32; r += 8)
        tile[r][tx] = W[(size_t)(k0 + r) * N3 + n0 + tx];
    __syncthreads();
    for (int r = ty; r < 32; r += 8) {
        float x = tile[tx][r];
        __nv_bfloat16 h = __float2bfloat16_rn(x);
        __nv_bfloat16 l = __float2bfloat16_rn(x - __bfloat162float(h));
        size_t o = (size_t)(n0 + r) * DIMV + k0 + tx;
        g_WThi[o] = __bfloat16_as_ushort(h);
        g_WTlo[o] = __bfloat16_as_ushort(l);
    }
}

// ---------------- Kernel 1: QKV GEMM (HMMA) + fused norm/rope epilogue ------
// CTA 256 thr (8 warps 2x4), tile M=128 x N=128, k-chunk 32, smem stride 40.
#define GA_HI 0
#define GA_LO 10240
#define GB_HI 20480
#define GB_LO 30720
#define G_SMEM 66048              // staging 128x129 f32 reuses the buffer

__global__ __launch_bounds__(256) void qkv_gemm_mma(
    const float* __restrict__ X, const float* __restrict__ cosb,
    const float* __restrict__ sinb, const float* __restrict__ bias,
    float* __restrict__ outdummy)
{
    extern __shared__ __align__(16) char smem[];
    const int tid = threadIdx.x, lane = tid & 31, wid = tid >> 5;
    const int g = lane >> 2, t = lane & 3;
    const int wy = wid >> 2, wx = wid & 3;          // warp tile 64x32
    const int m0 = blockIdx.y * 128, n0 = blockIdx.x * 128;

    float acc[4][4][4];
#pragma unroll
    for (int i = 0; i < 4; i++)
#pragma unroll
        for (int j = 0; j < 4; j++)
#pragma unroll
            for (int q = 0; q < 4; q++) acc[i][j][q] = 0.f;

    const int arow = tid >> 1, aseg = (tid & 1) * 16;

    for (int c = 0; c < 48; c++) {
        __syncthreads();
        // A: X fp32 -> hi/lo bf16 split
        {
            const float* xr = X + (size_t)(m0 + arow) * DIMV + c * 32 + aseg;
#pragma unroll
            for (int j = 0; j < 4; j++) {
                float4 v = *(const float4*)&xr[j * 4];
                uint32_t h01, l01, h23, l23;
                split2(v.x, v.y, h01, l01);
                split2(v.z, v.w, h23, l23);
                const int eo = arow * 40 + aseg + j * 4;
                *(uint2*)(smem + GA_HI + eo * 2) = make_uint2(h01, h23);
                *(uint2*)(smem + GA_LO + eo * 2) = make_uint2(l01, l23);
            }
        }
        // B: pre-split W^T
        {
            const size_t gb = (size_t)(n0 + arow) * DIMV + c * 32 + aseg;
            const int eo = arow * 40 + aseg;
            st8(smem + GB_HI + eo * 2,      *(const uint4*)&g_WThi[gb]);
            st8(smem + GB_HI + eo * 2 + 16, *(const uint4*)&g_WThi[gb + 8]);
            st8(smem + GB_LO + eo * 2,      *(const uint4*)&g_WTlo[gb]);
            st8(smem + GB_LO + eo * 2 + 16, *(const uint4*)&g_WTlo[gb + 8]);
        }
        __syncthreads();

#pragma unroll
        for (int kk = 0; kk < 32; kk += 16) {
            uint32_t aH[4][4], aL[4][4];
#pragma unroll
            for (int mt = 0; mt < 4; mt++) {
                const int r0 = wy * 64 + mt * 16;
                const int c0 = kk + 2 * t, c1 = kk + 8 + 2 * t;
                aH[mt][0] = *(const uint32_t*)(smem + GA_HI + ((r0 + g) * 40 + c0) * 2);
                aH[mt][1] = *(const uint32_t*)(smem + GA_HI + ((r0 + g + 8) * 40 + c0) * 2);
                aH[mt][2] = *(const uint32_t*)(smem + GA_HI + ((r0 + g) * 40 + c1) * 2);
                aH[mt][3] = *(const uint32_t*)(smem + GA_HI + ((r0 + g + 8) * 40 + c1) * 2);
                aL[mt][0] = *(const uint32_t*)(smem + GA_LO + ((r0 + g) * 40 + c0) * 2);
                aL[mt][1] = *(const uint32_t*)(smem + GA_LO + ((r0 + g + 8) * 40 + c0) * 2);
                aL[mt][2] = *(const uint32_t*)(smem + GA_LO + ((r0 + g) * 40 + c1) * 2);
                aL[mt][3] = *(const uint32_t*)(smem + GA_LO + ((r0 + g + 8) * 40 + c1) * 2);
            }
#pragma unroll
            for (int nt = 0; nt < 4; nt++) {
                const int nr = wx * 32 + nt * 8 + g;
                const uint32_t bH0 = *(const uint32_t*)(smem + GB_HI + (nr * 40 + kk + 2 * t) * 2);
                const uint32_t bH1 = *(const uint32_t*)(smem + GB_HI + (nr * 40 + kk + 8 + 2 * t) * 2);
                const uint32_t bL0 = *(const uint32_t*)(smem + GB_LO + (nr * 40 + kk + 2 * t) * 2);
                const uint32_t bL1 = *(const uint32_t*)(smem + GB_LO + (nr * 40 + kk + 8 + 2 * t) * 2);
#pragma unroll
                for (int mt = 0; mt < 4; mt++) {
                    mma16816(acc[mt][nt], aH[mt][0], aH[mt][1], aH[mt][2], aH[mt][3], bH0, bH1);
                    mma16816(acc[mt][nt], aH[mt][0], aH[mt][1], aH[mt][2], aH[mt][3], bL0, bL1);
                    mma16816(acc[mt][nt], aL[mt][0], aL[mt][1], aL[mt][2], aL[mt][3], bH0, bH1);
                }
            }
        }
    }

    // Stage accumulators to smem (stride 129 f32 -> conflict-free column reads)
    __syncthreads();
    float* st = (float*)smem;
#pragma unroll
    for (int mt = 0; mt < 4; mt++)
#pragma unroll
        for (int nt = 0; nt < 4; nt++) {
            const int r = wy * 64 + mt * 16 + g;
            const int cx = wx * 32 + nt * 8 + 2 * t;
            st[r * 129 + cx]           = acc[mt][nt][0];
            st[r * 129 + cx + 1]       = acc[mt][nt][1];
            st[(r + 8) * 129 + cx]     = acc[mt][nt][2];
            st[(r + 8) * 129 + cx + 1] = acc[mt][nt][3];
        }
    __syncthreads();

    // Epilogue: thread = (headSel, row)
    const int headSel = tid >> 7, row = tid & 127;
    const int m = m0 + row, b = m >> 12, s = m & (SEQ - 1);
    const int sec = n0 / DIMV, nloc = n0 % DIMV;
    const int h = nloc / HD + headSel;
    const int bh = b * NH + h;
    const int nb = n0 + headSel * 64;

    float v[64];
#pragma unroll
    for (int j = 0; j < 64; j++)
        v[j] = st[row * 129 + headSel * 64 + j] + bias[nb + j];

    if (sec < 2) {
        float ss = 0.f;
#pragma unroll
        for (int j = 0; j < 64; j++) ss = fmaf(v[j], v[j], ss);
        const float rinv = rsqrtf(ss * (1.0f / 64.0f) + 1e-6f);
        uint32_t ph[32], pl[32];
#pragma unroll
        for (int i = 0; i < 32; i++) {
            const float cc = cosb[s * HD + 2 * i], sn = sinb[s * HD + 2 * i];
            const float x1 = v[2 * i] * rinv, x2 = v[2 * i + 1] * rinv;
            split2(fmaf(x1, cc, -x2 * sn), fmaf(x2, cc, x1 * sn), ph[i], pl[i]);
        }
        unsigned short* dh = (sec == 0 ? g_Qhi : g_Khi) + ((size_t)bh * SEQ + s) * HD;
        unsigned short* dl = (sec == 0 ? g_Qlo : g_Klo) + ((size_t)bh * SEQ + s) * HD;
#pragma unroll
        for (int q = 0; q < 8; q++) {
            *(uint4*)(dh + q * 8) = make_uint4(ph[4*q], ph[4*q+1], ph[4*q+2], ph[4*q+3]);
            *(uint4*)(dl + q * 8) = make_uint4(pl[4*q], pl[4*q+1], pl[4*q+2], pl[4*q+3]);
        }
    } else {
        // V: transposed coalesced store [bh][d][s]
#pragma unroll
        for (int d = 0; d < 64; d++) {
            __nv_bfloat16 hb = __float2bfloat16_rn(v[d]);
            __nv_bfloat16 lb = __float2bfloat16_rn(v[d] - __bfloat162float(hb));
            const size_t o = ((size_t)bh * HD + d) * SEQ + s;
            g_Vhi[o] = __bfloat16_as_ushort(hb);
            g_Vlo[o] = __bfloat16_as_ushort(lb);
        }
    }
    (void)outdummy;
}

// ---------------- Kernel 2: flash attention (HMMA) --------------------------
// CTA 256 thr (8 warps), 128 q-rows, 64-key tiles, smem stride 72.
#define AQ_HI 0
#define AQ_LO 18432
#define AK_HI 36864
#define AK_LO 46080
#define AV_HI 55296
#define AV_LO 64512
#define A_SMEM 73728

__global__ __launch_bounds__(256) void attn_mma(float* __restrict__ out) {
    extern __shared__ __align__(16) char smem[];
    const int tid = threadIdx.x, lane = tid & 31, wid = tid >> 5;
    const int g = lane >> 2, t = lane & 3;
    const int bh = blockIdx.y, b = bh / NH, h = bh % NH;
    const int q0 = blockIdx.x * 128;

    // Q tile (resident): row = tid>>1, 32-elem half
    {
        const int row = tid >> 1, seg = (tid & 1) * 32;
        const size_t gq = ((size_t)bh * SEQ + q0 + row) * HD + seg;
        const int eo = row * 72 + seg;
#pragma unroll
        for (int j = 0; j < 4; j++) {
            st8(smem + AQ_HI + (eo + j * 8) * 2, *(const uint4*)&g_Qhi[gq + j * 8]);
            st8(smem + AQ_LO + (eo + j * 8) * 2, *(const uint4*)&g_Qlo[gq + j * 8]);
        }
    }

    float oacc[8][4];
#pragma unroll
    for (int i = 0; i < 8; i++)
#pragma unroll
        for (int j = 0; j < 4; j++) oacc[i][j] = 0.f;
    float rs0 = 0.f, rs1 = 0.f;
    const float KSC = 0.125f * 1.44269504089f;

    const int krow = tid >> 2, kseg = (tid & 3) * 16;

    for (int kt = 0; kt < SEQ / 64; kt++) {
        __syncthreads();
        // K tile [key][d], V^T tile [d][key]
        {
            const size_t gk = ((size_t)bh * SEQ + kt * 64 + krow) * HD + kseg;
            const size_t gv = ((size_t)bh * HD + krow) * SEQ + kt * 64 + kseg;
            const int eo = krow * 72 + kseg;
            st8(smem + AK_HI + eo * 2,        *(const uint4*)&g_Khi[gk]);
            st8(smem + AK_HI + (eo + 8) * 2,  *(const uint4*)&g_Khi[gk + 8]);
            st8(smem + AK_LO + eo * 2,        *(const uint4*)&g_Klo[gk]);
            st8(smem + AK_LO + (eo + 8) * 2,  *(const uint4*)&g_Klo[gk + 8]);
            st8(smem + AV_HI + eo * 2,        *(const uint4*)&g_Vhi[gv]);
            st8(smem + AV_HI + (eo + 8) * 2,  *(const uint4*)&g_Vhi[gv + 8]);
            st8(smem + AV_LO + eo * 2,        *(const uint4*)&g_Vlo[gv]);
            st8(smem + AV_LO + (eo + 8) * 2,  *(const uint4*)&g_Vlo[gv + 8]);
        }
        __syncthreads();

        // S = Q K^T : warp m-tile = wid*16, 8 n-tiles of 8 keys
        float sacc[8][4];
#pragma unroll
        for (int i = 0; i < 8; i++)
#pragma unroll
            for (int j = 0; j < 4; j++) sacc[i][j] = 0.f;

#pragma unroll
        for (int kq = 0; kq < 4; kq++) {
            const int r0 = wid * 16;
            const int c0 = kq * 16 + 2 * t, c1 = kq * 16 + 8 + 2 * t;
            uint32_t qH[4], qL[4];
            qH[0] = *(const uint32_t*)(smem + AQ_HI + ((r0 + g) * 72 + c0) * 2);
            qH[1] = *(const uint32_t*)(smem + AQ_HI + ((r0 + g + 8) * 72 + c0) * 2);
            qH[2] = *(const uint32_t*)(smem + AQ_HI + ((r0 + g) * 72 + c1) * 2);
            qH[3] = *(const uint32_t*)(smem + AQ_HI + ((r0 + g + 8) * 72 + c1) * 2);
            qL[0] = *(const uint32_t*)(smem + AQ_LO + ((r0 + g) * 72 + c0) * 2);
            qL[1] = *(const uint32_t*)(smem + AQ_LO + ((r0 + g + 8) * 72 + c0) * 2);
            qL[2] = *(const uint32_t*)(smem + AQ_LO + ((r0 + g) * 72 + c1) * 2);
            qL[3] = *(const uint32_t*)(smem + AQ_LO + ((r0 + g + 8) * 72 + c1) * 2);
#pragma unroll
            for (int nt = 0; nt < 8; nt++) {
                const int nr = nt * 8 + g;
                const uint32_t bH0 = *(const uint32_t*)(smem + AK_HI + (nr * 72 + c0) * 2);
                const uint32_t bH1 = *(const uint32_t*)(smem + AK_HI + (nr * 72 + c1) * 2);
                const uint32_t bL0 = *(const uint32_t*)(smem + AK_LO + (nr * 72 + c0) * 2);
                const uint32_t bL1 = *(const uint32_t*)(smem + AK_LO + (nr * 72 + c1) * 2);
                mma16816(sacc[nt], qH[0], qH[1], qH[2], qH[3], bH0, bH1);
                mma16816(sacc[nt], qH[0], qH[1], qH[2], qH[3], bL0, bL1);
                mma16816(sacc[nt], qL[0], qL[1], qL[2], qL[3], bH0, bH1);
            }
        }

        // Softmax (no max pass: |s*scale| <= 8), repack P into A-fragments
        uint32_t paH[8][2], paL[8][2];
#pragma unroll
        for (int nt = 0; nt < 8; nt++) {
            const float e0 = exp2p(sacc[nt][0] * KSC);
            const float e1 = exp2p(sacc[nt][1] * KSC);
            const float e2 = exp2p(sacc[nt][2] * KSC);
            const float e3 = exp2p(sacc[nt][3] * KSC);
            rs0 += e0 + e1;
            rs1 += e2 + e3;
            split2(e0, e1, paH[nt][0], paL[nt][0]);
            split2(e2, e3, paH[nt][1], paL[nt][1]);
        }

        // O += P V : k = keys (4 k16 tiles), n = d (8 tiles)
#pragma unroll
        for (int k2 = 0; k2 < 4; k2++) {
            const uint32_t aH0 = paH[2*k2][0],   aH1 = paH[2*k2][1];
            const uint32_t aH2 = paH[2*k2+1][0], aH3 = paH[2*k2+1][1];
            const uint32_t aL0 = paL[2*k2][0],   aL1 = paL[2*k2][1];
            const uint32_t aL2 = paL[2*k2+1][0], aL3 = paL[2*k2+1][1];
            const int c0 = k2 * 16 + 2 * t, c1 = k2 * 16 + 8 + 2 * t;
#pragma unroll
            for (int nt = 0; nt < 8; nt++) {
                const int nr = nt * 8 + g;
                const uint32_t bH0 = *(const uint32_t*)(smem + AV_HI + (nr * 72 + c0) * 2);
                const uint32_t bH1 = *(const uint32_t*)(smem + AV_HI + (nr * 72 + c1) * 2);
                const uint32_t bL0 = *(const uint32_t*)(smem + AV_LO + (nr * 72 + c0) * 2);
                const uint32_t bL1 = *(const uint32_t*)(smem + AV_LO + (nr * 72 + c1) * 2);
                mma16816(oacc[nt], aH0, aH1, aH2, aH3, bH0, bH1);
                mma16816(oacc[nt], aH0, aH1, aH2, aH3, bL0, bL1);
                mma16816(oacc[nt], aL0, aL1, aL2, aL3, bH0, bH1);
            }
        }
    }

    // Row-sum reduce within quad (lanes sharing g), normalize, write
    rs0 += __shfl_xor_sync(0xffffffffu, rs0, 1);
    rs0 += __shfl_xor_sync(0xffffffffu, rs0, 2);
    rs1 += __shfl_xor_sync(0xffffffffu, rs1, 1);
    rs1 += __shfl_xor_sync(0xffffffffu, rs1, 2);
    const float inv0 = 1.0f / rs0, inv1 = 1.0f / rs1;

    const int s0 = q0 + wid * 16 + g, s1 = s0 + 8;
    float* o0 = &out[((size_t)b * SEQ + s0) * DIMV + h * HD];
    float* o1 = &out[((size_t)b * SEQ + s1) * DIMV + h * HD];
#pragma unroll
    for (int nt = 0; nt < 8; nt++) {
        const int cx = nt * 8 + 2 * t;
        *(float2*)(o0 + cx) = make_float2(oacc[nt][0] * inv0, oacc[nt][1] * inv0);
        *(float2*)(o1 + cx) = make_float2(oacc[nt][2] * inv1, oacc[nt][3] * inv1);
    }
}

// ---------------------------------------------------------------------------
extern "C" void kernel_launch(void* const* d_in, const int* in_sizes, int n_in,
                              void* d_out, int out_size) {
    const float* x    = (const float*)d_in[0];
    const float* cosb = (const float*)d_in[1];
    const float* sinb = (const float*)d_in[2];
    const float* w    = (const float*)d_in[3];
    const float* bq   = (const float*)d_in[4];

    static int cfg = 0;
    if (!cfg) {
        cudaFuncSetAttribute(qkv_gemm_mma, cudaFuncAttributeMaxDynamicSharedMemorySize, G_SMEM);
        cudaFuncSetAttribute(attn_mma,     cudaFuncAttributeMaxDynamicSharedMemorySize, A_SMEM);
        cfg = 1;
    }

    wt_prep<<<dim3(N3 / 32, DIMV / 32), 256>>>(w);
    qkv_gemm_mma<<<dim3(N3 / 128, NT / 128), 256, G_SMEM>>>(x, cosb, sinb, bq, (float*)d_out);
    attn_mma<<<dim3(SEQ / 128, BHN), 256, A_SMEM>>>((float*)d_out);
}

// round 5
// speedup vs baseline: 4.0700x; 1.4784x over previous
#include <cuda_runtime.h>
#include <cuda_fp16.h>
#include <math.h>
#include <stdint.h>

#define SEQ   4096
#define BATCH 4
#define NH    24
#define HD    64
#define DIMV  1536
#define N3    4608
#define NT    16384
#define BHN   96

__device__ __align__(16) unsigned short g_WThi[(size_t)N3 * DIMV];    // [n][k] fp16
__device__ __align__(16) unsigned short g_Qhi[(size_t)BHN * SEQ * HD]; // [bh][s][d]
__device__ __align__(16) unsigned short g_Qlo[(size_t)BHN * SEQ * HD];
__device__ __align__(16) unsigned short g_Khi[(size_t)BHN * SEQ * HD];
__device__ __align__(16) unsigned short g_Vhi[(size_t)BHN * HD * SEQ]; // [bh][d][s]

// ---------------- helpers ----------------
__device__ __forceinline__ void mma16816(float* c, uint32_t a0, uint32_t a1,
                                         uint32_t a2, uint32_t a3,
                                         uint32_t b0, uint32_t b1) {
    asm volatile(
        "mma.sync.aligned.m16n8k16.row.col.f32.f16.f16.f32 "
        "{%0,%1,%2,%3},{%4,%5,%6,%7},{%8,%9},{%0,%1,%2,%3};"
        : "+f"(c[0]), "+f"(c[1]), "+f"(c[2]), "+f"(c[3])
        : "r"(a0), "r"(a1), "r"(a2), "r"(a3), "r"(b0), "r"(b1));
}

__device__ __forceinline__ void split2h(float a, float b, uint32_t& hi, uint32_t& lo) {
    __half ha = __float2half_rn(a), hb = __float2half_rn(b);
    __half la = __float2half_rn(a - __half2float(ha));
    __half lb = __float2half_rn(b - __half2float(hb));
    hi = ((uint32_t)__half_as_ushort(hb) << 16) | (uint32_t)__half_as_ushort(ha);
    lo = ((uint32_t)__half_as_ushort(lb) << 16) | (uint32_t)__half_as_ushort(la);
}

// FMA-pipe exp2 (no MUFU). |y| <= 12 in our use.
__device__ __forceinline__ float exp2p(float y) {
    float r = y + 12582912.0f;
    float nf = r - 12582912.0f;
    float f = y - nf;
    int n = __float_as_int(r) - 0x4B400000;
    float p = 0.00133335581f;
    p = fmaf(p, f, 0.00961812910f);
    p = fmaf(p, f, 0.0555041087f);
    p = fmaf(p, f, 0.240226507f);
    p = fmaf(p, f, 0.693147182f);
    p = fmaf(p, f, 1.0f);
    return p * __int_as_float((n + 127) << 23);
}

#define CP_ASYNC16(dst, src) \
    asm volatile("cp.async.ca.shared.global [%0], [%1], 16;" :: "r"(dst), "l"(src))
#define CP_COMMIT() asm volatile("cp.async.commit_group;" ::: "memory")
#define CP_WAIT0()  asm volatile("cp.async.wait_group 0;" ::: "memory")

__device__ __forceinline__ uint32_t smem_u32(const void* p) {
    uint32_t a;
    asm("{ .reg .u64 t; cvta.to.shared.u64 t, %1; cvt.u32.u64 %0, t; }" : "=r"(a) : "l"(p));
    return a;
}

// ---------------- Kernel 0: W transpose + fp16 hi ----------------
__global__ __launch_bounds__(256) void wt_prep(const float* __restrict__ W) {
    __shared__ float tile[32][33];
    const int n0 = blockIdx.x * 32, k0 = blockIdx.y * 32;
    const int tx = threadIdx.x & 31, ty = threadIdx.x >> 5;
    for (int r = ty; r < 32; r += 8)
        tile[r][tx] = W[(size_t)(k0 + r) * N3 + n0 + tx];
    __syncthreads();
    for (int r = ty; r < 32; r += 8) {
        g_WThi[(size_t)(n0 + r) * DIMV + k0 + tx] =
            __half_as_ushort(__float2half_rn(tile[tx][r]));
    }
}

// ---------------- Kernel 1: QKV GEMM (fp16 HMMA, 2-product) -----------------
// CTA 256 thr (8 warps 2x4), tile M=128 x N=128, k-chunk 32, smem stride 40.
#define GA_HI 0
#define GA_LO 10240
#define GB_HI 20480
#define G_SMEM 66048              // epilogue staging 128x129 f32 reuses buffer

__global__ __launch_bounds__(256) void qkv_gemm_mma(
    const float* __restrict__ X, const float* __restrict__ cosb,
    const float* __restrict__ sinb, const float* __restrict__ bias)
{
    extern __shared__ __align__(16) char smem[];
    const int tid = threadIdx.x, lane = tid & 31, wid = tid >> 5;
    const int g = lane >> 2, t = lane & 3;
    const int wy = wid >> 2, wx = wid & 3;          // warp tile 64x32
    const int m0 = blockIdx.y * 128, n0 = blockIdx.x * 128;

    float acc[4][4][4];
#pragma unroll
    for (int i = 0; i < 4; i++)
#pragma unroll
        for (int j = 0; j < 4; j++)
#pragma unroll
            for (int q = 0; q < 4; q++) acc[i][j][q] = 0.f;

    const int arow = tid >> 1, aseg = (tid & 1) * 16;

    for (int c = 0; c < 48; c++) {
        __syncthreads();
        // A: X fp32 -> hi/lo fp16 split
        {
            const float* xr = X + (size_t)(m0 + arow) * DIMV + c * 32 + aseg;
#pragma unroll
            for (int j = 0; j < 4; j++) {
                float4 v = *(const float4*)&xr[j * 4];
                uint32_t h01, l01, h23, l23;
                split2h(v.x, v.y, h01, l01);
                split2h(v.z, v.w, h23, l23);
                const int eo = arow * 40 + aseg + j * 4;
                *(uint2*)(smem + GA_HI + eo * 2) = make_uint2(h01, h23);
                *(uint2*)(smem + GA_LO + eo * 2) = make_uint2(l01, l23);
            }
        }
        // B: W^T hi fp16
        {
            const size_t gb = (size_t)(n0 + arow) * DIMV + c * 32 + aseg;
            const int eo = arow * 40 + aseg;
            *(uint4*)(smem + GB_HI + eo * 2)      = *(const uint4*)&g_WThi[gb];
            *(uint4*)(smem + GB_HI + eo * 2 + 16) = *(const uint4*)&g_WThi[gb + 8];
        }
        __syncthreads();

#pragma unroll
        for (int kk = 0; kk < 32; kk += 16) {
            uint32_t aH[4][4], aL[4][4];
#pragma unroll
            for (int mt = 0; mt < 4; mt++) {
                const int r0 = wy * 64 + mt * 16;
                const int c0 = kk + 2 * t, c1 = kk + 8 + 2 * t;
                aH[mt][0] = *(const uint32_t*)(smem + GA_HI + ((r0 + g) * 40 + c0) * 2);
                aH[mt][1] = *(const uint32_t*)(smem + GA_HI + ((r0 + g + 8) * 40 + c0) * 2);
                aH[mt][2] = *(const uint32_t*)(smem + GA_HI + ((r0 + g) * 40 + c1) * 2);
                aH[mt][3] = *(const uint32_t*)(smem + GA_HI + ((r0 + g + 8) * 40 + c1) * 2);
                aL[mt][0] = *(const uint32_t*)(smem + GA_LO + ((r0 + g) * 40 + c0) * 2);
                aL[mt][1] = *(const uint32_t*)(smem + GA_LO + ((r0 + g + 8) * 40 + c0) * 2);
                aL[mt][2] = *(const uint32_t*)(smem + GA_LO + ((r0 + g) * 40 + c1) * 2);
                aL[mt][3] = *(const uint32_t*)(smem + GA_LO + ((r0 + g + 8) * 40 + c1) * 2);
            }
#pragma unroll
            for (int nt = 0; nt < 4; nt++) {
                const int nr = wx * 32 + nt * 8 + g;
                const uint32_t bH0 = *(const uint32_t*)(smem + GB_HI + (nr * 40 + kk + 2 * t) * 2);
                const uint32_t bH1 = *(const uint32_t*)(smem + GB_HI + (nr * 40 + kk + 8 + 2 * t) * 2);
#pragma unroll
                for (int mt = 0; mt < 4; mt++) {
                    mma16816(acc[mt][nt], aH[mt][0], aH[mt][1], aH[mt][2], aH[mt][3], bH0, bH1);
                    mma16816(acc[mt][nt], aL[mt][0], aL[mt][1], aL[mt][2], aL[mt][3], bH0, bH1);
                }
            }
        }
    }

    // Stage accumulators (stride 129 f32)
    __syncthreads();
    float* st = (float*)smem;
#pragma unroll
    for (int mt = 0; mt < 4; mt++)
#pragma unroll
        for (int nt = 0; nt < 4; nt++) {
            const int r = wy * 64 + mt * 16 + g;
            const int cx = wx * 32 + nt * 8 + 2 * t;
            st[r * 129 + cx]           = acc[mt][nt][0];
            st[r * 129 + cx + 1]       = acc[mt][nt][1];
            st[(r + 8) * 129 + cx]     = acc[mt][nt][2];
            st[(r + 8) * 129 + cx + 1] = acc[mt][nt][3];
        }
    __syncthreads();

    // Epilogue
    const int headSel = tid >> 7, row = tid & 127;
    const int m = m0 + row, b = m >> 12, s = m & (SEQ - 1);
    const int sec = n0 / DIMV, nloc = n0 % DIMV;
    const int h = nloc / HD + headSel;
    const int bh = b * NH + h;
    const int nb = n0 + headSel * 64;

    float v[64];
#pragma unroll
    for (int j = 0; j < 64; j++)
        v[j] = st[row * 129 + headSel * 64 + j] + bias[nb + j];

    if (sec < 2) {
        float ss = 0.f;
#pragma unroll
        for (int j = 0; j < 64; j++) ss = fmaf(v[j], v[j], ss);
        const float rinv = rsqrtf(ss * (1.0f / 64.0f) + 1e-6f);
        uint32_t ph[32], pl[32];
#pragma unroll
        for (int i = 0; i < 32; i++) {
            const float cc = cosb[s * HD + 2 * i], sn = sinb[s * HD + 2 * i];
            const float x1 = v[2 * i] * rinv, x2 = v[2 * i + 1] * rinv;
            split2h(fmaf(x1, cc, -x2 * sn), fmaf(x2, cc, x1 * sn), ph[i], pl[i]);
        }
        if (sec == 0) {
            unsigned short* dh = g_Qhi + ((size_t)bh * SEQ + s) * HD;
            unsigned short* dl = g_Qlo + ((size_t)bh * SEQ + s) * HD;
#pragma unroll
            for (int q = 0; q < 8; q++) {
                *(uint4*)(dh + q * 8) = make_uint4(ph[4*q], ph[4*q+1], ph[4*q+2], ph[4*q+3]);
                *(uint4*)(dl + q * 8) = make_uint4(pl[4*q], pl[4*q+1], pl[4*q+2], pl[4*q+3]);
            }
        } else {
            unsigned short* dh = g_Khi + ((size_t)bh * SEQ + s) * HD;
#pragma unroll
            for (int q = 0; q < 8; q++)
                *(uint4*)(dh + q * 8) = make_uint4(ph[4*q], ph[4*q+1], ph[4*q+2], ph[4*q+3]);
        }
    } else {
        // V: transposed store [bh][d][s], hi fp16
#pragma unroll
        for (int d = 0; d < 64; d++)
            g_Vhi[((size_t)bh * HD + d) * SEQ + s] =
                __half_as_ushort(__float2half_rn(v[d]));
    }
}

// ---------------- Kernel 2: flash attention (fp16 HMMA, 2-product) ----------
// CTA 256 thr (8 warps x 16 q-rows), 64-key tiles, double-buffered cp.async.
#define AQ_HI 0
#define AQ_LO 18432
#define AK(buf) (36864 + (buf) * 9216)
#define AV(buf) (55296 + (buf) * 9216)
#define A_SMEM 73728

__global__ __launch_bounds__(256) void attn_mma(float* __restrict__ out) {
    extern __shared__ __align__(16) char smem[];
    const uint32_t sbase = smem_u32(smem);
    const int tid = threadIdx.x, lane = tid & 31, wid = tid >> 5;
    const int g = lane >> 2, t = lane & 3;
    const int bh = blockIdx.y, b = bh / NH, h = bh % NH;
    const int q0 = blockIdx.x * 128;

    // Q tile (resident): row = tid>>1, 32-elem half
    {
        const int row = tid >> 1, seg = (tid & 1) * 32;
        const size_t gq = ((size_t)bh * SEQ + q0 + row) * HD + seg;
        const uint32_t eo = (row * 72 + seg) * 2;
#pragma unroll
        for (int j = 0; j < 4; j++) {
            *(uint4*)(smem + AQ_HI + eo + j * 16) = *(const uint4*)&g_Qhi[gq + j * 8];
            *(uint4*)(smem + AQ_LO + eo + j * 16) = *(const uint4*)&g_Qlo[gq + j * 8];
        }
    }

    float oacc[8][4];
#pragma unroll
    for (int i = 0; i < 8; i++)
#pragma unroll
        for (int j = 0; j < 4; j++) oacc[i][j] = 0.f;
    float rs0 = 0.f, rs1 = 0.f;
    const float KSC = 0.125f * 1.44269504089f;

    const int krow = tid >> 2, kseg = (tid & 3) * 16;
    const uint32_t keo = (krow * 72 + kseg) * 2;

    // preload tile 0 into buffer 0
    {
        const size_t gk = ((size_t)bh * SEQ + krow) * HD + kseg;
        const size_t gv = ((size_t)bh * HD + krow) * SEQ + kseg;
        CP_ASYNC16(sbase + AK(0) + keo,      (const char*)&g_Khi[gk]);
        CP_ASYNC16(sbase + AK(0) + keo + 16, (const char*)&g_Khi[gk + 8]);
        CP_ASYNC16(sbase + AV(0) + keo,      (const char*)&g_Vhi[gv]);
        CP_ASYNC16(sbase + AV(0) + keo + 16, (const char*)&g_Vhi[gv + 8]);
        CP_COMMIT();
    }

    for (int kt = 0; kt < SEQ / 64; kt++) {
        CP_WAIT0();
        __syncthreads();
        if (kt + 1 < SEQ / 64) {
            const int nb2 = (kt + 1) & 1;
            const size_t gk = ((size_t)bh * SEQ + (kt + 1) * 64 + krow) * HD + kseg;
            const size_t gv = ((size_t)bh * HD + krow) * SEQ + (kt + 1) * 64 + kseg;
            CP_ASYNC16(sbase + AK(nb2) + keo,      (const char*)&g_Khi[gk]);
            CP_ASYNC16(sbase + AK(nb2) + keo + 16, (const char*)&g_Khi[gk + 8]);
            CP_ASYNC16(sbase + AV(nb2) + keo,      (const char*)&g_Vhi[gv]);
            CP_ASYNC16(sbase + AV(nb2) + keo + 16, (const char*)&g_Vhi[gv + 8]);
            CP_COMMIT();
        }
        const int buf = kt & 1;
        const char* kbase = smem + AK(buf);
        const char* vbase = smem + AV(buf);

        // S = Q K^T
        float sacc[8][4];
#pragma unroll
        for (int i = 0; i < 8; i++)
#pragma unroll
            for (int j = 0; j < 4; j++) sacc[i][j] = 0.f;

#pragma unroll
        for (int kq = 0; kq < 4; kq++) {
            const int r0 = wid * 16;
            const int c0 = kq * 16 + 2 * t, c1 = kq * 16 + 8 + 2 * t;
            uint32_t qH[4], qL[4];
            qH[0] = *(const uint32_t*)(smem + AQ_HI + ((r0 + g) * 72 + c0) * 2);
            qH[1] = *(const uint32_t*)(smem + AQ_HI + ((r0 + g + 8) * 72 + c0) * 2);
            qH[2] = *(const uint32_t*)(smem + AQ_HI + ((r0 + g) * 72 + c1) * 2);
            qH[3] = *(const uint32_t*)(smem + AQ_HI + ((r0 + g + 8) * 72 + c1) * 2);
            qL[0] = *(const uint32_t*)(smem + AQ_LO + ((r0 + g) * 72 + c0) * 2);
            qL[1] = *(const uint32_t*)(smem + AQ_LO + ((r0 + g + 8) * 72 + c0) * 2);
            qL[2] = *(const uint32_t*)(smem + AQ_LO + ((r0 + g) * 72 + c1) * 2);
            qL[3] = *(const uint32_t*)(smem + AQ_LO + ((r0 + g + 8) * 72 + c1) * 2);
#pragma unroll
            for (int nt = 0; nt < 8; nt++) {
                const int nr = nt * 8 + g;
                const uint32_t bH0 = *(const uint32_t*)(kbase + (nr * 72 + c0) * 2);
                const uint32_t bH1 = *(const uint32_t*)(kbase + (nr * 72 + c1) * 2);
                mma16816(sacc[nt], qH[0], qH[1], qH[2], qH[3], bH0, bH1);
                mma16816(sacc[nt], qL[0], qL[1], qL[2], qL[3], bH0, bH1);
            }
        }

        // Softmax (bounded: |s*KSC| <= 11.6), repack P into A-fragments
        uint32_t paH[8][2], paL[8][2];
#pragma unroll
        for (int nt = 0; nt < 8; nt++) {
            const float e0 = exp2p(sacc[nt][0] * KSC);
            const float e1 = exp2p(sacc[nt][1] * KSC);
            const float e2 = exp2p(sacc[nt][2] * KSC);
            const float e3 = exp2p(sacc[nt][3] * KSC);
            rs0 += e0 + e1;
            rs1 += e2 + e3;
            split2h(e0, e1, paH[nt][0], paL[nt][0]);
            split2h(e2, e3, paH[nt][1], paL[nt][1]);
        }

        // O += P V
#pragma unroll
        for (int k2 = 0; k2 < 4; k2++) {
            const uint32_t aH0 = paH[2*k2][0],   aH1 = paH[2*k2][1];
            const uint32_t aH2 = paH[2*k2+1][0], aH3 = paH[2*k2+1][1];
            const uint32_t aL0 = paL[2*k2][0],   aL1 = paL[2*k2][1];
            const uint32_t aL2 = paL[2*k2+1][0], aL3 = paL[2*k2+1][1];
            const int c0 = k2 * 16 + 2 * t, c1 = k2 * 16 + 8 + 2 * t;
#pragma unroll
            for (int nt = 0; nt < 8; nt++) {
                const int nr = nt * 8 + g;
                const uint32_t bH0 = *(const uint32_t*)(vbase + (nr * 72 + c0) * 2);
                const uint32_t bH1 = *(const uint32_t*)(vbase + (nr * 72 + c1) * 2);
                mma16816(oacc[nt], aH0, aH1, aH2, aH3, bH0, bH1);
                mma16816(oacc[nt], aL0, aL1, aL2, aL3, bH0, bH1);
            }
        }
    }

    // Quad rowsum reduce, normalize, write
    rs0 += __shfl_xor_sync(0xffffffffu, rs0, 1);
    rs0 += __shfl_xor_sync(0xffffffffu, rs0, 2);
    rs1 += __shfl_xor_sync(0xffffffffu, rs1, 1);
    rs1 += __shfl_xor_sync(0xffffffffu, rs1, 2);
    const float inv0 = 1.0f / rs0, inv1 = 1.0f / rs1;

    const int s0 = q0 + wid * 16 + g, s1 = s0 + 8;
    float* o0 = &out[((size_t)b * SEQ + s0) * DIMV + h * HD];
    float* o1 = &out[((size_t)b * SEQ + s1) * DIMV + h * HD];
#pragma unroll
    for (int nt = 0; nt < 8; nt++) {
        const int cx = nt * 8 + 2 * t;
        *(float2*)(o0 + cx) = make_float2(oacc[nt][0] * inv0, oacc[nt][1] * inv0);
        *(float2*)(o1 + cx) = make_float2(oacc[nt][2] * inv1, oacc[nt][3] * inv1);
    }
}

// ---------------------------------------------------------------------------
extern "C" void kernel_launch(void* const* d_in, const int* in_sizes, int n_in,
                              void* d_out, int out_size) {
    const float* x    = (const float*)d_in[0];
    const float* cosb = (const float*)d_in[1];
    const float* sinb = (const float*)d_in[2];
    const float* w    = (const float*)d_in[3];
    const float* bq   = (const float*)d_in[4];

    cudaFuncSetAttribute(qkv_gemm_mma, cudaFuncAttributeMaxDynamicSharedMemorySize, G_SMEM);
    cudaFuncSetAttribute(attn_mma,     cudaFuncAttributeMaxDynamicSharedMemorySize, A_SMEM);

    wt_prep<<<dim3(N3 / 32, DIMV / 32), 256>>>(w);
    qkv_gemm_mma<<<dim3(N3 / 128, NT / 128), 256, G_SMEM>>>(x, cosb, sinb, bq);
    attn_mma<<<dim3(SEQ / 128, BHN), 256, A_SMEM>>>((float*)d_out);
}

// round 6
// speedup vs baseline: 5.6424x; 1.3863x over previous
#include <cuda_runtime.h>
#include <cuda_fp16.h>
#include <math.h>
#include <stdint.h>

#define SEQ   4096
#define BATCH 4
#define NH    24
#define HD    64
#define DIMV  1536
#define N3    4608
#define NT    16384
#define BHN   96

__device__ __align__(16) unsigned short g_WThi[(size_t)N3 * DIMV];    // [n][k] fp16
__device__ __align__(16) unsigned short g_Qhi[(size_t)BHN * SEQ * HD]; // [bh][s][d]
__device__ __align__(16) unsigned short g_Khi[(size_t)BHN * SEQ * HD];
__device__ __align__(16) unsigned short g_Vhi[(size_t)BHN * HD * SEQ]; // [bh][d][s]

// ---------------- helpers ----------------
__device__ __forceinline__ void mma16816(float* c, uint32_t a0, uint32_t a1,
                                         uint32_t a2, uint32_t a3,
                                         uint32_t b0, uint32_t b1) {
    asm volatile(
        "mma.sync.aligned.m16n8k16.row.col.f32.f16.f16.f32 "
        "{%0,%1,%2,%3},{%4,%5,%6,%7},{%8,%9},{%0,%1,%2,%3};"
        : "+f"(c[0]), "+f"(c[1]), "+f"(c[2]), "+f"(c[3])
        : "r"(a0), "r"(a1), "r"(a2), "r"(a3), "r"(b0), "r"(b1));
}

__device__ __forceinline__ uint32_t packh(float a, float b) {
    __half2 h = __floats2half2_rn(a, b);
    return *(uint32_t*)&h;
}

// FMA-pipe exp2 (no MUFU). |y| <= 12 in our use.
__device__ __forceinline__ float exp2p(float y) {
    float r = y + 12582912.0f;
    float nf = r - 12582912.0f;
    float f = y - nf;
    int n = __float_as_int(r) - 0x4B400000;
    float p = 0.00133335581f;
    p = fmaf(p, f, 0.00961812910f);
    p = fmaf(p, f, 0.0555041087f);
    p = fmaf(p, f, 0.240226507f);
    p = fmaf(p, f, 0.693147182f);
    p = fmaf(p, f, 1.0f);
    return p * __int_as_float((n + 127) << 23);
}

#define CP_ASYNC16(dst, src) \
    asm volatile("cp.async.ca.shared.global [%0], [%1], 16;" :: "r"(dst), "l"(src))
#define CP_COMMIT() asm volatile("cp.async.commit_group;" ::: "memory")
#define CP_WAIT0()  asm volatile("cp.async.wait_group 0;" ::: "memory")

__device__ __forceinline__ uint32_t smem_u32(const void* p) {
    uint32_t a;
    asm("{ .reg .u64 t; cvta.to.shared.u64 t, %1; cvt.u32.u64 %0, t; }" : "=r"(a) : "l"(p));
    return a;
}

// ---------------- Kernel 0: W transpose + fp16 ----------------
__global__ __launch_bounds__(256) void wt_prep(const float* __restrict__ W) {
    __shared__ float tile[32][33];
    const int n0 = blockIdx.x * 32, k0 = blockIdx.y * 32;
    const int tx = threadIdx.x & 31, ty = threadIdx.x >> 5;
    for (int r = ty; r < 32; r += 8)
        tile[r][tx] = W[(size_t)(k0 + r) * N3 + n0 + tx];
    __syncthreads();
    for (int r = ty; r < 32; r += 8) {
        g_WThi[(size_t)(n0 + r) * DIMV + k0 + tx] =
            __half_as_ushort(__float2half_rn(tile[tx][r]));
    }
}

// ---------------- Kernel 1: QKV GEMM (single-pass fp16 HMMA) ----------------
// CTA 256 thr (8 warps 2x4), tile M=128 x N=128, k-chunk 32, smem stride 40.
#define GA_HI 0
#define GB_HI 10240
#define G_SMEM 66048              // epilogue staging 128x129 f32 reuses buffer

__global__ __launch_bounds__(256) void qkv_gemm_mma(
    const float* __restrict__ X, const float* __restrict__ cosb,
    const float* __restrict__ sinb, const float* __restrict__ bias)
{
    extern __shared__ __align__(16) char smem[];
    const int tid = threadIdx.x, lane = tid & 31, wid = tid >> 5;
    const int g = lane >> 2, t = lane & 3;
    const int wy = wid >> 2, wx = wid & 3;          // warp tile 64x32
    const int m0 = blockIdx.y * 128, n0 = blockIdx.x * 128;

    float acc[4][4][4];
#pragma unroll
    for (int i = 0; i < 4; i++)
#pragma unroll
        for (int j = 0; j < 4; j++)
#pragma unroll
            for (int q = 0; q < 4; q++) acc[i][j][q] = 0.f;

    const int arow = tid >> 1, aseg = (tid & 1) * 16;

    for (int c = 0; c < 48; c++) {
        __syncthreads();
        // A: X fp32 -> fp16
        {
            const float* xr = X + (size_t)(m0 + arow) * DIMV + c * 32 + aseg;
            const int eo = arow * 40 + aseg;
#pragma unroll
            for (int j = 0; j < 2; j++) {
                float4 v0 = *(const float4*)&xr[j * 8];
                float4 v1 = *(const float4*)&xr[j * 8 + 4];
                *(uint4*)(smem + GA_HI + (eo + j * 8) * 2) =
                    make_uint4(packh(v0.x, v0.y), packh(v0.z, v0.w),
                               packh(v1.x, v1.y), packh(v1.z, v1.w));
            }
        }
        // B: W^T fp16
        {
            const size_t gb = (size_t)(n0 + arow) * DIMV + c * 32 + aseg;
            const int eo = arow * 40 + aseg;
            *(uint4*)(smem + GB_HI + eo * 2)      = *(const uint4*)&g_WThi[gb];
            *(uint4*)(smem + GB_HI + eo * 2 + 16) = *(const uint4*)&g_WThi[gb + 8];
        }
        __syncthreads();

#pragma unroll
        for (int kk = 0; kk < 32; kk += 16) {
            uint32_t aH[4][4];
#pragma unroll
            for (int mt = 0; mt < 4; mt++) {
                const int r0 = wy * 64 + mt * 16;
                const int c0 = kk + 2 * t, c1 = kk + 8 + 2 * t;
                aH[mt][0] = *(const uint32_t*)(smem + GA_HI + ((r0 + g) * 40 + c0) * 2);
                aH[mt][1] = *(const uint32_t*)(smem + GA_HI + ((r0 + g + 8) * 40 + c0) * 2);
                aH[mt][2] = *(const uint32_t*)(smem + GA_HI + ((r0 + g) * 40 + c1) * 2);
                aH[mt][3] = *(const uint32_t*)(smem + GA_HI + ((r0 + g + 8) * 40 + c1) * 2);
            }
#pragma unroll
            for (int nt = 0; nt < 4; nt++) {
                const int nr = wx * 32 + nt * 8 + g;
                const uint32_t bH0 = *(const uint32_t*)(smem + GB_HI + (nr * 40 + kk + 2 * t) * 2);
                const uint32_t bH1 = *(const uint32_t*)(smem + GB_HI + (nr * 40 + kk + 8 + 2 * t) * 2);
#pragma unroll
                for (int mt = 0; mt < 4; mt++)
                    mma16816(acc[mt][nt], aH[mt][0], aH[mt][1], aH[mt][2], aH[mt][3], bH0, bH1);
            }
        }
    }

    // Stage accumulators (stride 129 f32)
    __syncthreads();
    float* st = (float*)smem;
#pragma unroll
    for (int mt = 0; mt < 4; mt++)
#pragma unroll
        for (int nt = 0; nt < 4; nt++) {
            const int r = wy * 64 + mt * 16 + g;
            const int cx = wx * 32 + nt * 8 + 2 * t;
            st[r * 129 + cx]           = acc[mt][nt][0];
            st[r * 129 + cx + 1]       = acc[mt][nt][1];
            st[(r + 8) * 129 + cx]     = acc[mt][nt][2];
            st[(r + 8) * 129 + cx + 1] = acc[mt][nt][3];
        }
    __syncthreads();

    // Epilogue
    const int headSel = tid >> 7, row = tid & 127;
    const int m = m0 + row, b = m >> 12, s = m & (SEQ - 1);
    const int sec = n0 / DIMV, nloc = n0 % DIMV;
    const int h = nloc / HD + headSel;
    const int bh = b * NH + h;
    const int nb = n0 + headSel * 64;

    float v[64];
#pragma unroll
    for (int j = 0; j < 64; j++)
        v[j] = st[row * 129 + headSel * 64 + j] + bias[nb + j];

    if (sec < 2) {
        float ss = 0.f;
#pragma unroll
        for (int j = 0; j < 64; j++) ss = fmaf(v[j], v[j], ss);
        const float rinv = rsqrtf(ss * (1.0f / 64.0f) + 1e-6f);
        uint32_t ph[32];
#pragma unroll
        for (int i = 0; i < 32; i++) {
            const float cc = cosb[s * HD + 2 * i], sn = sinb[s * HD + 2 * i];
            const float x1 = v[2 * i] * rinv, x2 = v[2 * i + 1] * rinv;
            ph[i] = packh(fmaf(x1, cc, -x2 * sn), fmaf(x2, cc, x1 * sn));
        }
        unsigned short* dh = (sec == 0 ? g_Qhi : g_Khi) + ((size_t)bh * SEQ + s) * HD;
#pragma unroll
        for (int q = 0; q < 8; q++)
            *(uint4*)(dh + q * 8) = make_uint4(ph[4*q], ph[4*q+1], ph[4*q+2], ph[4*q+3]);
    } else {
        // V: transposed store [bh][d][s], fp16
#pragma unroll
        for (int d = 0; d < 64; d++)
            g_Vhi[((size_t)bh * HD + d) * SEQ + s] =
                __half_as_ushort(__float2half_rn(v[d]));
    }
}

// ---------------- Kernel 2: flash attention (single-pass fp16 HMMA) ---------
// CTA 256 thr (8 warps x 16 q-rows), 64-key tiles, double-buffered cp.async.
#define AQ_HI 0
#define AK(buf) (18432 + (buf) * 9216)
#define AV(buf) (36864 + (buf) * 9216)
#define A_SMEM 55296

__global__ __launch_bounds__(256) void attn_mma(float* __restrict__ out) {
    extern __shared__ __align__(16) char smem[];
    const uint32_t sbase = smem_u32(smem);
    const int tid = threadIdx.x, lane = tid & 31, wid = tid >> 5;
    const int g = lane >> 2, t = lane & 3;
    const int bh = blockIdx.y, b = bh / NH, h = bh % NH;
    const int q0 = blockIdx.x * 128;

    // Q tile (resident): row = tid>>1, 32-elem half
    {
        const int row = tid >> 1, seg = (tid & 1) * 32;
        const size_t gq = ((size_t)bh * SEQ + q0 + row) * HD + seg;
        const uint32_t eo = (row * 72 + seg) * 2;
#pragma unroll
        for (int j = 0; j < 4; j++)
            *(uint4*)(smem + AQ_HI + eo + j * 16) = *(const uint4*)&g_Qhi[gq + j * 8];
    }

    float oacc[8][4];
#pragma unroll
    for (int i = 0; i < 8; i++)
#pragma unroll
        for (int j = 0; j < 4; j++) oacc[i][j] = 0.f;
    float rs0 = 0.f, rs1 = 0.f;
    const float KSC = 0.125f * 1.44269504089f;

    const int krow = tid >> 2, kseg = (tid & 3) * 16;
    const uint32_t keo = (krow * 72 + kseg) * 2;

    // preload tile 0 into buffer 0
    {
        const size_t gk = ((size_t)bh * SEQ + krow) * HD + kseg;
        const size_t gv = ((size_t)bh * HD + krow) * SEQ + kseg;
        CP_ASYNC16(sbase + AK(0) + keo,      (const char*)&g_Khi[gk]);
        CP_ASYNC16(sbase + AK(0) + keo + 16, (const char*)&g_Khi[gk + 8]);
        CP_ASYNC16(sbase + AV(0) + keo,      (const char*)&g_Vhi[gv]);
        CP_ASYNC16(sbase + AV(0) + keo + 16, (const char*)&g_Vhi[gv + 8]);
        CP_COMMIT();
    }

    for (int kt = 0; kt < SEQ / 64; kt++) {
        CP_WAIT0();
        __syncthreads();
        if (kt + 1 < SEQ / 64) {
            const int nb2 = (kt + 1) & 1;
            const size_t gk = ((size_t)bh * SEQ + (kt + 1) * 64 + krow) * HD + kseg;
            const size_t gv = ((size_t)bh * HD + krow) * SEQ + (kt + 1) * 64 + kseg;
            CP_ASYNC16(sbase + AK(nb2) + keo,      (const char*)&g_Khi[gk]);
            CP_ASYNC16(sbase + AK(nb2) + keo + 16, (const char*)&g_Khi[gk + 8]);
            CP_ASYNC16(sbase + AV(nb2) + keo,      (const char*)&g_Vhi[gv]);
            CP_ASYNC16(sbase + AV(nb2) + keo + 16, (const char*)&g_Vhi[gv + 8]);
            CP_COMMIT();
        }
        const int buf = kt & 1;
        const char* kbase = smem + AK(buf);
        const char* vbase = smem + AV(buf);

        // S = Q K^T
        float sacc[8][4];
#pragma unroll
        for (int i = 0; i < 8; i++)
#pragma unroll
            for (int j = 0; j < 4; j++) sacc[i][j] = 0.f;

#pragma unroll
        for (int kq = 0; kq < 4; kq++) {
            const int r0 = wid * 16;
            const int c0 = kq * 16 + 2 * t, c1 = kq * 16 + 8 + 2 * t;
            uint32_t qH[4];
            qH[0] = *(const uint32_t*)(smem + AQ_HI + ((r0 + g) * 72 + c0) * 2);
            qH[1] = *(const uint32_t*)(smem + AQ_HI + ((r0 + g + 8) * 72 + c0) * 2);
            qH[2] = *(const uint32_t*)(smem + AQ_HI + ((r0 + g) * 72 + c1) * 2);
            qH[3] = *(const uint32_t*)(smem + AQ_HI + ((r0 + g + 8) * 72 + c1) * 2);
#pragma unroll
            for (int nt = 0; nt < 8; nt++) {
                const int nr = nt * 8 + g;
                const uint32_t bH0 = *(const uint32_t*)(kbase + (nr * 72 + c0) * 2);
                const uint32_t bH1 = *(const uint32_t*)(kbase + (nr * 72 + c1) * 2);
                mma16816(sacc[nt], qH[0], qH[1], qH[2], qH[3], bH0, bH1);
            }
        }

        // Softmax (bounded: |s*KSC| <= 11.6), repack P into A-fragments
        uint32_t paH[8][2];
#pragma unroll
        for (int nt = 0; nt < 8; nt++) {
            const float e0 = exp2p(sacc[nt][0] * KSC);
            const float e1 = exp2p(sacc[nt][1] * KSC);
            const float e2 = exp2p(sacc[nt][2] * KSC);
            const float e3 = exp2p(sacc[nt][3] * KSC);
            rs0 += e0 + e1;
            rs1 += e2 + e3;
            paH[nt][0] = packh(e0, e1);
            paH[nt][1] = packh(e2, e3);
        }

        // O += P V
#pragma unroll
        for (int k2 = 0; k2 < 4; k2++) {
            const uint32_t aH0 = paH[2*k2][0],   aH1 = paH[2*k2][1];
            const uint32_t aH2 = paH[2*k2+1][0], aH3 = paH[2*k2+1][1];
            const int c0 = k2 * 16 + 2 * t, c1 = k2 * 16 + 8 + 2 * t;
#pragma unroll
            for (int nt = 0; nt < 8; nt++) {
                const int nr = nt * 8 + g;
                const uint32_t bH0 = *(const uint32_t*)(vbase + (nr * 72 + c0) * 2);
                const uint32_t bH1 = *(const uint32_t*)(vbase + (nr * 72 + c1) * 2);
                mma16816(oacc[nt], aH0, aH1, aH2, aH3, bH0, bH1);
            }
        }
    }

    // Quad rowsum reduce, normalize, write
    rs0 += __shfl_xor_sync(0xffffffffu, rs0, 1);
    rs0 += __shfl_xor_sync(0xffffffffu, rs0, 2);
    rs1 += __shfl_xor_sync(0xffffffffu, rs1, 1);
    rs1 += __shfl_xor_sync(0xffffffffu, rs1, 2);
    const float inv0 = 1.0f / rs0, inv1 = 1.0f / rs1;

    const int s0 = q0 + wid * 16 + g, s1 = s0 + 8;
    float* o0 = &out[((size_t)b * SEQ + s0) * DIMV + h * HD];
    float* o1 = &out[((size_t)b * SEQ + s1) * DIMV + h * HD];
#pragma unroll
    for (int nt = 0; nt < 8; nt++) {
        const int cx = nt * 8 + 2 * t;
        *(float2*)(o0 + cx) = make_float2(oacc[nt][0] * inv0, oacc[nt][1] * inv0);
        *(float2*)(o1 + cx) = make_float2(oacc[nt][2] * inv1, oacc[nt][3] * inv1);
    }
}

// ---------------------------------------------------------------------------
extern "C" void kernel_launch(void* const* d_in, const int* in_sizes, int n_in,
                              void* d_out, int out_size) {
    const float* x    = (const float*)d_in[0];
    const float* cosb = (const float*)d_in[1];
    const float* sinb = (const float*)d_in[2];
    const float* w    = (const float*)d_in[3];
    const float* bq   = (const float*)d_in[4];

    cudaFuncSetAttribute(qkv_gemm_mma, cudaFuncAttributeMaxDynamicSharedMemorySize, G_SMEM);
    cudaFuncSetAttribute(attn_mma,     cudaFuncAttributeMaxDynamicSharedMemorySize, A_SMEM);

    wt_prep<<<dim3(N3 / 32, DIMV / 32), 256>>>(w);
    qkv_gemm_mma<<<dim3(N3 / 128, NT / 128), 256, G_SMEM>>>(x, cosb, sinb, bq);
    attn_mma<<<dim3(SEQ / 128, BHN), 256, A_SMEM>>>((float*)d_out);
}

// round 7
// speedup vs baseline: 5.8364x; 1.0344x over previous
#include <cuda_runtime.h>
#include <cuda_fp16.h>
#include <math.h>
#include <stdint.h>

#define SEQ   4096
#define BATCH 4
#define NH    24
#define HD    64
#define DIMV  1536
#define N3    4608
#define NT    16384
#define BHN   96

__device__ __align__(16) unsigned short g_WThi[(size_t)N3 * DIMV];    // [n][k] fp16
__device__ __align__(16) unsigned short g_Qhi[(size_t)BHN * SEQ * HD]; // [bh][s][d]
__device__ __align__(16) unsigned short g_Khi[(size_t)BHN * SEQ * HD];
__device__ __align__(16) unsigned short g_Vhi[(size_t)BHN * HD * SEQ]; // [bh][d][s]

// ---------------- helpers ----------------
__device__ __forceinline__ void mma16816(float* c, uint32_t a0, uint32_t a1,
                                         uint32_t a2, uint32_t a3,
                                         uint32_t b0, uint32_t b1) {
    asm volatile(
        "mma.sync.aligned.m16n8k16.row.col.f32.f16.f16.f32 "
        "{%0,%1,%2,%3},{%4,%5,%6,%7},{%8,%9},{%0,%1,%2,%3};"
        : "+f"(c[0]), "+f"(c[1]), "+f"(c[2]), "+f"(c[3])
        : "r"(a0), "r"(a1), "r"(a2), "r"(a3), "r"(b0), "r"(b1));
}

__device__ __forceinline__ uint32_t packh(float a, float b) {
    __half2 h = __floats2half2_rn(a, b);
    return *(uint32_t*)&h;
}

// FMA-pipe exp2 (no MUFU). |y| <= 12 in our use.
__device__ __forceinline__ float exp2p(float y) {
    float r = y + 12582912.0f;
    float nf = r - 12582912.0f;
    float f = y - nf;
    int n = __float_as_int(r) - 0x4B400000;
    float p = 0.00133335581f;
    p = fmaf(p, f, 0.00961812910f);
    p = fmaf(p, f, 0.0555041087f);
    p = fmaf(p, f, 0.240226507f);
    p = fmaf(p, f, 0.693147182f);
    p = fmaf(p, f, 1.0f);
    return p * __int_as_float((n + 127) << 23);
}

#define CP_ASYNC16(dst, src) \
    asm volatile("cp.async.ca.shared.global [%0], [%1], 16;" :: "r"(dst), "l"(src))
#define CP_COMMIT() asm volatile("cp.async.commit_group;" ::: "memory")
#define CP_WAIT0()  asm volatile("cp.async.wait_group 0;" ::: "memory")

__device__ __forceinline__ uint32_t smem_u32(const void* p) {
    uint32_t a;
    asm("{ .reg .u64 t; cvta.to.shared.u64 t, %1; cvt.u32.u64 %0, t; }" : "=r"(a) : "l"(p));
    return a;
}

// ---------------- Kernel 0: W transpose + fp16 ----------------
__global__ __launch_bounds__(256) void wt_prep(const float* __restrict__ W) {
    __shared__ float tile[32][33];
    const int n0 = blockIdx.x * 32, k0 = blockIdx.y * 32;
    const int tx = threadIdx.x & 31, ty = threadIdx.x >> 5;
    for (int r = ty; r < 32; r += 8)
        tile[r][tx] = W[(size_t)(k0 + r) * N3 + n0 + tx];
    __syncthreads();
    for (int r = ty; r < 32; r += 8) {
        g_WThi[(size_t)(n0 + r) * DIMV + k0 + tx] =
            __half_as_ushort(__float2half_rn(tile[tx][r]));
    }
}

// ---------------- Kernel 1: QKV GEMM (fp16 HMMA, double-buffered) -----------
// CTA 256 thr (8 warps 2x4), tile M=128 x N=128, k-chunk 32, smem stride 40.
#define GA(buf) ((buf) * 10240)
#define GB(buf) (20480 + (buf) * 10240)
#define G_SMEM 66048              // epilogue staging 128x129 f32 reuses buffer

__global__ __launch_bounds__(256) void qkv_gemm_mma(
    const float* __restrict__ X, const float* __restrict__ cosb,
    const float* __restrict__ sinb, const float* __restrict__ bias)
{
    extern __shared__ __align__(16) char smem[];
    const uint32_t sbase = smem_u32(smem);
    const int tid = threadIdx.x, lane = tid & 31, wid = tid >> 5;
    const int g = lane >> 2, t = lane & 3;
    const int wy = wid >> 2, wx = wid & 3;          // warp tile 64x32
    const int m0 = blockIdx.y * 128, n0 = blockIdx.x * 128;

    float acc[4][4][4];
#pragma unroll
    for (int i = 0; i < 4; i++)
#pragma unroll
        for (int j = 0; j < 4; j++)
#pragma unroll
            for (int q = 0; q < 4; q++) acc[i][j][q] = 0.f;

    const int arow = tid >> 1, aseg = (tid & 1) * 16;
    const int eo = arow * 40 + aseg;                 // element offset in tile
    const float* xrow = X + (size_t)(m0 + arow) * DIMV + aseg;
    const size_t gbrow = (size_t)(n0 + arow) * DIMV + aseg;

    float4 xv0, xv1, xv2, xv3;

    // Prologue: chunk 0 -> buffer 0
    {
        xv0 = *(const float4*)&xrow[0];
        xv1 = *(const float4*)&xrow[4];
        xv2 = *(const float4*)&xrow[8];
        xv3 = *(const float4*)&xrow[12];
        CP_ASYNC16(sbase + GB(0) + eo * 2,      (const char*)&g_WThi[gbrow]);
        CP_ASYNC16(sbase + GB(0) + eo * 2 + 16, (const char*)&g_WThi[gbrow + 8]);
        CP_COMMIT();
        *(uint4*)(smem + GA(0) + eo * 2) =
            make_uint4(packh(xv0.x, xv0.y), packh(xv0.z, xv0.w),
                       packh(xv1.x, xv1.y), packh(xv1.z, xv1.w));
        *(uint4*)(smem + GA(0) + eo * 2 + 16) =
            make_uint4(packh(xv2.x, xv2.y), packh(xv2.z, xv2.w),
                       packh(xv3.x, xv3.y), packh(xv3.z, xv3.w));
        CP_WAIT0();
        __syncthreads();
    }

    for (int c = 0; c < 48; c++) {
        const int buf = c & 1, nbuf = buf ^ 1;
        if (c + 1 < 48) {
            // Prefetch chunk c+1: X -> regs, W -> cp.async into other buffer
            const float* xr = xrow + (c + 1) * 32;
            xv0 = *(const float4*)&xr[0];
            xv1 = *(const float4*)&xr[4];
            xv2 = *(const float4*)&xr[8];
            xv3 = *(const float4*)&xr[12];
            const size_t gb = gbrow + (c + 1) * 32;
            CP_ASYNC16(sbase + GB(nbuf) + eo * 2,      (const char*)&g_WThi[gb]);
            CP_ASYNC16(sbase + GB(nbuf) + eo * 2 + 16, (const char*)&g_WThi[gb + 8]);
            CP_COMMIT();
        }

        // MMA on buffer buf
#pragma unroll
        for (int kk = 0; kk < 32; kk += 16) {
            uint32_t aH[4][4];
#pragma unroll
            for (int mt = 0; mt < 4; mt++) {
                const int r0 = wy * 64 + mt * 16;
                const int c0 = kk + 2 * t, c1 = kk + 8 + 2 * t;
                aH[mt][0] = *(const uint32_t*)(smem + GA(buf) + ((r0 + g) * 40 + c0) * 2);
                aH[mt][1] = *(const uint32_t*)(smem + GA(buf) + ((r0 + g + 8) * 40 + c0) * 2);
                aH[mt][2] = *(const uint32_t*)(smem + GA(buf) + ((r0 + g) * 40 + c1) * 2);
                aH[mt][3] = *(const uint32_t*)(smem + GA(buf) + ((r0 + g + 8) * 40 + c1) * 2);
            }
#pragma unroll
            for (int nt = 0; nt < 4; nt++) {
                const int nr = wx * 32 + nt * 8 + g;
                const uint32_t bH0 = *(const uint32_t*)(smem + GB(buf) + (nr * 40 + kk + 2 * t) * 2);
                const uint32_t bH1 = *(const uint32_t*)(smem + GB(buf) + (nr * 40 + kk + 8 + 2 * t) * 2);
#pragma unroll
                for (int mt = 0; mt < 4; mt++)
                    mma16816(acc[mt][nt], aH[mt][0], aH[mt][1], aH[mt][2], aH[mt][3], bH0, bH1);
            }
        }

        if (c + 1 < 48) {
            // Convert prefetched X into the other buffer, wait B, sync
            *(uint4*)(smem + GA(nbuf) + eo * 2) =
                make_uint4(packh(xv0.x, xv0.y), packh(xv0.z, xv0.w),
                           packh(xv1.x, xv1.y), packh(xv1.z, xv1.w));
            *(uint4*)(smem + GA(nbuf) + eo * 2 + 16) =
                make_uint4(packh(xv2.x, xv2.y), packh(xv2.z, xv2.w),
                           packh(xv3.x, xv3.y), packh(xv3.z, xv3.w));
            CP_WAIT0();
        }
        __syncthreads();
    }

    // Stage accumulators (stride 129 f32)
    float* st = (float*)smem;
#pragma unroll
    for (int mt = 0; mt < 4; mt++)
#pragma unroll
        for (int nt = 0; nt < 4; nt++) {
            const int r = wy * 64 + mt * 16 + g;
            const int cx = wx * 32 + nt * 8 + 2 * t;
            st[r * 129 + cx]           = acc[mt][nt][0];
            st[r * 129 + cx + 1]       = acc[mt][nt][1];
            st[(r + 8) * 129 + cx]     = acc[mt][nt][2];
            st[(r + 8) * 129 + cx + 1] = acc[mt][nt][3];
        }
    __syncthreads();

    // Epilogue
    const int headSel = tid >> 7, row = tid & 127;
    const int m = m0 + row, b = m >> 12, s = m & (SEQ - 1);
    const int sec = n0 / DIMV, nloc = n0 % DIMV;
    const int h = nloc / HD + headSel;
    const int bh = b * NH + h;
    const int nb = n0 + headSel * 64;

    float v[64];
#pragma unroll
    for (int j = 0; j < 64; j++)
        v[j] = st[row * 129 + headSel * 64 + j] + bias[nb + j];

    if (sec < 2) {
        float ss = 0.f;
#pragma unroll
        for (int j = 0; j < 64; j++) ss = fmaf(v[j], v[j], ss);
        const float rinv = rsqrtf(ss * (1.0f / 64.0f) + 1e-6f);
        uint32_t ph[32];
#pragma unroll
        for (int i = 0; i < 32; i++) {
            const float cc = cosb[s * HD + 2 * i], sn = sinb[s * HD + 2 * i];
            const float x1 = v[2 * i] * rinv, x2 = v[2 * i + 1] * rinv;
            ph[i] = packh(fmaf(x1, cc, -x2 * sn), fmaf(x2, cc, x1 * sn));
        }
        unsigned short* dh = (sec == 0 ? g_Qhi : g_Khi) + ((size_t)bh * SEQ + s) * HD;
#pragma unroll
        for (int q = 0; q < 8; q++)
            *(uint4*)(dh + q * 8) = make_uint4(ph[4*q], ph[4*q+1], ph[4*q+2], ph[4*q+3]);
    } else {
        // V: transposed store [bh][d][s], fp16
#pragma unroll
        for (int d = 0; d < 64; d++)
            g_Vhi[((size_t)bh * HD + d) * SEQ + s] =
                __half_as_ushort(__float2half_rn(v[d]));
    }
}

// ---------------- Kernel 2: flash attention (fp16 HMMA, Q in regs) ----------
// CTA 256 thr (8 warps x 16 q-rows), 64-key tiles, double-buffered cp.async.
#define AK(buf) ((buf) * 9216)
#define AV(buf) (18432 + (buf) * 9216)
#define A_SMEM 36864

__global__ __launch_bounds__(256) void attn_mma(float* __restrict__ out) {
    extern __shared__ __align__(16) char smem[];
    const uint32_t sbase = smem_u32(smem);
    const int tid = threadIdx.x, lane = tid & 31, wid = tid >> 5;
    const int g = lane >> 2, t = lane & 3;
    const int bh = blockIdx.y, b = bh / NH, h = bh % NH;
    const int q0 = blockIdx.x * 128;

    // Q fragments in registers (fragment words are contiguous u32 in [s][d])
    uint32_t qf[4][4];
    {
        const size_t rbase = (size_t)bh * SEQ + q0 + wid * 16;
#pragma unroll
        for (int kq = 0; kq < 4; kq++) {
            const int c0 = kq * 16 + 2 * t, c1 = c0 + 8;
            qf[kq][0] = *(const uint32_t*)&g_Qhi[(rbase + g) * HD + c0];
            qf[kq][1] = *(const uint32_t*)&g_Qhi[(rbase + g + 8) * HD + c0];
            qf[kq][2] = *(const uint32_t*)&g_Qhi[(rbase + g) * HD + c1];
            qf[kq][3] = *(const uint32_t*)&g_Qhi[(rbase + g + 8) * HD + c1];
        }
    }

    float oacc[8][4];
#pragma unroll
    for (int i = 0; i < 8; i++)
#pragma unroll
        for (int j = 0; j < 4; j++) oacc[i][j] = 0.f;
    float rs0 = 0.f, rs1 = 0.f;
    const float KSC = 0.125f * 1.44269504089f;

    const int krow = tid >> 2, kseg = (tid & 3) * 16;
    const uint32_t keo = (krow * 72 + kseg) * 2;

    // preload tile 0 into buffer 0
    {
        const size_t gk = ((size_t)bh * SEQ + krow) * HD + kseg;
        const size_t gv = ((size_t)bh * HD + krow) * SEQ + kseg;
        CP_ASYNC16(sbase + AK(0) + keo,      (const char*)&g_Khi[gk]);
        CP_ASYNC16(sbase + AK(0) + keo + 16, (const char*)&g_Khi[gk + 8]);
        CP_ASYNC16(sbase + AV(0) + keo,      (const char*)&g_Vhi[gv]);
        CP_ASYNC16(sbase + AV(0) + keo + 16, (const char*)&g_Vhi[gv + 8]);
        CP_COMMIT();
    }

    for (int kt = 0; kt < SEQ / 64; kt++) {
        CP_WAIT0();
        __syncthreads();
        if (kt + 1 < SEQ / 64) {
            const int nb2 = (kt + 1) & 1;
            const size_t gk = ((size_t)bh * SEQ + (kt + 1) * 64 + krow) * HD + kseg;
            const size_t gv = ((size_t)bh * HD + krow) * SEQ + (kt + 1) * 64 + kseg;
            CP_ASYNC16(sbase + AK(nb2) + keo,      (const char*)&g_Khi[gk]);
            CP_ASYNC16(sbase + AK(nb2) + keo + 16, (const char*)&g_Khi[gk + 8]);
            CP_ASYNC16(sbase + AV(nb2) + keo,      (const char*)&g_Vhi[gv]);
            CP_ASYNC16(sbase + AV(nb2) + keo + 16, (const char*)&g_Vhi[gv + 8]);
            CP_COMMIT();
        }
        const int buf = kt & 1;
        const char* kbase = smem + AK(buf);
        const char* vbase = smem + AV(buf);

        // S = Q K^T
        float sacc[8][4];
#pragma unroll
        for (int i = 0; i < 8; i++)
#pragma unroll
            for (int j = 0; j < 4; j++) sacc[i][j] = 0.f;

#pragma unroll
        for (int kq = 0; kq < 4; kq++) {
            const int c0 = kq * 16 + 2 * t, c1 = kq * 16 + 8 + 2 * t;
#pragma unroll
            for (int nt = 0; nt < 8; nt++) {
                const int nr = nt * 8 + g;
                const uint32_t bH0 = *(const uint32_t*)(kbase + (nr * 72 + c0) * 2);
                const uint32_t bH1 = *(const uint32_t*)(kbase + (nr * 72 + c1) * 2);
                mma16816(sacc[nt], qf[kq][0], qf[kq][1], qf[kq][2], qf[kq][3], bH0, bH1);
            }
        }

        // Softmax (bounded: |s*KSC| <= 11.6), repack P into A-fragments
        uint32_t paH[8][2];
#pragma unroll
        for (int nt = 0; nt < 8; nt++) {
            const float e0 = exp2p(sacc[nt][0] * KSC);
            const float e1 = exp2p(sacc[nt][1] * KSC);
            const float e2 = exp2p(sacc[nt][2] * KSC);
            const float e3 = exp2p(sacc[nt][3] * KSC);
            rs0 += e0 + e1;
            rs1 += e2 + e3;
            paH[nt][0] = packh(e0, e1);
            paH[nt][1] = packh(e2, e3);
        }

        // O += P V
#pragma unroll
        for (int k2 = 0; k2 < 4; k2++) {
            const uint32_t aH0 = paH[2*k2][0],   aH1 = paH[2*k2][1];
            const uint32_t aH2 = paH[2*k2+1][0], aH3 = paH[2*k2+1][1];
            const int c0 = k2 * 16 + 2 * t, c1 = k2 * 16 + 8 + 2 * t;
#pragma unroll
            for (int nt = 0; nt < 8; nt++) {
                const int nr = nt * 8 + g;
                const uint32_t bH0 = *(const uint32_t*)(vbase + (nr * 72 + c0) * 2);
                const uint32_t bH1 = *(const uint32_t*)(vbase + (nr * 72 + c1) * 2);
                mma16816(oacc[nt], aH0, aH1, aH2, aH3, bH0, bH1);
            }
        }
    }

    // Quad rowsum reduce, normalize, write
    rs0 += __shfl_xor_sync(0xffffffffu, rs0, 1);
    rs0 += __shfl_xor_sync(0xffffffffu, rs0, 2);
    rs1 += __shfl_xor_sync(0xffffffffu, rs1, 1);
    rs1 += __shfl_xor_sync(0xffffffffu, rs1, 2);
    const float inv0 = 1.0f / rs0, inv1 = 1.0f / rs1;

    const int s0 = q0 + wid * 16 + g, s1 = s0 + 8;
    float* o0 = &out[((size_t)b * SEQ + s0) * DIMV + h * HD];
    float* o1 = &out[((size_t)b * SEQ + s1) * DIMV + h * HD];
#pragma unroll
    for (int nt = 0; nt < 8; nt++) {
        const int cx = nt * 8 + 2 * t;
        *(float2*)(o0 + cx) = make_float2(oacc[nt][0] * inv0, oacc[nt][1] * inv0);
        *(float2*)(o1 + cx) = make_float2(oacc[nt][2] * inv1, oacc[nt][3] * inv1);
    }
}

// ---------------------------------------------------------------------------
extern "C" void kernel_launch(void* const* d_in, const int* in_sizes, int n_in,
                              void* d_out, int out_size) {
    const float* x    = (const float*)d_in[0];
    const float* cosb = (const float*)d_in[1];
    const float* sinb = (const float*)d_in[2];
    const float* w    = (const float*)d_in[3];
    const float* bq   = (const float*)d_in[4];

    cudaFuncSetAttribute(qkv_gemm_mma, cudaFuncAttributeMaxDynamicSharedMemorySize, G_SMEM);
    cudaFuncSetAttribute(attn_mma,     cudaFuncAttributeMaxDynamicSharedMemorySize, A_SMEM);

    wt_prep<<<dim3(N3 / 32, DIMV / 32), 256>>>(w);
    qkv_gemm_mma<<<dim3(N3 / 128, NT / 128), 256, G_SMEM>>>(x, cosb, sinb, bq);
    attn_mma<<<dim3(SEQ / 128, BHN), 256, A_SMEM>>>((float*)d_out);
}

// round 8
// speedup vs baseline: 6.6035x; 1.1314x over previous
#include <cuda_runtime.h>
#include <cuda_fp16.h>
#include <math.h>
#include <stdint.h>

#define SEQ   4096
#define BATCH 4
#define NH    24
#define HD    64
#define DIMV  1536
#define N3    4608
#define NT    16384
#define BHN   96

__device__ __align__(16) unsigned short g_WThi[(size_t)N3 * DIMV];    // [n][k] fp16
__device__ __align__(16) unsigned short g_Qhi[(size_t)BHN * SEQ * HD]; // [bh][s][d] (pre-scaled by 0.125*log2e)
__device__ __align__(16) unsigned short g_Khi[(size_t)BHN * SEQ * HD];
__device__ __align__(16) unsigned short g_Vhi[(size_t)BHN * HD * SEQ]; // [bh][d][s]

// ---------------- helpers ----------------
__device__ __forceinline__ void mma16816(float* c, uint32_t a0, uint32_t a1,
                                         uint32_t a2, uint32_t a3,
                                         uint32_t b0, uint32_t b1) {
    asm volatile(
        "mma.sync.aligned.m16n8k16.row.col.f32.f16.f16.f32 "
        "{%0,%1,%2,%3},{%4,%5,%6,%7},{%8,%9},{%0,%1,%2,%3};"
        : "+f"(c[0]), "+f"(c[1]), "+f"(c[2]), "+f"(c[3])
        : "r"(a0), "r"(a1), "r"(a2), "r"(a3), "r"(b0), "r"(b1));
}

__device__ __forceinline__ uint32_t packh(float a, float b) {
    __half2 h = __floats2half2_rn(a, b);
    return *(uint32_t*)&h;
}

// MUFU exp2 — separate pipe from FMA/tensor, 1 issue slot per exp
__device__ __forceinline__ float ex2(float y) {
    float r;
    asm("ex2.approx.f32 %0, %1;" : "=f"(r) : "f"(y));
    return r;
}

#define CP_ASYNC16(dst, src) \
    asm volatile("cp.async.ca.shared.global [%0], [%1], 16;" :: "r"(dst), "l"(src))
#define CP_COMMIT() asm volatile("cp.async.commit_group;" ::: "memory")
#define CP_WAIT0()  asm volatile("cp.async.wait_group 0;" ::: "memory")

__device__ __forceinline__ uint32_t smem_u32(const void* p) {
    uint32_t a;
    asm("{ .reg .u64 t; cvta.to.shared.u64 t, %1; cvt.u32.u64 %0, t; }" : "=r"(a) : "l"(p));
    return a;
}

// ---------------- Kernel 0: W transpose + fp16 ----------------
__global__ __launch_bounds__(256) void wt_prep(const float* __restrict__ W) {
    __shared__ float tile[32][33];
    const int n0 = blockIdx.x * 32, k0 = blockIdx.y * 32;
    const int tx = threadIdx.x & 31, ty = threadIdx.x >> 5;
    for (int r = ty; r < 32; r += 8)
        tile[r][tx] = W[(size_t)(k0 + r) * N3 + n0 + tx];
    __syncthreads();
    for (int r = ty; r < 32; r += 8) {
        g_WThi[(size_t)(n0 + r) * DIMV + k0 + tx] =
            __half_as_ushort(__float2half_rn(tile[tx][r]));
    }
}

// ---------------- Kernel 1: QKV GEMM (fp16 HMMA, double-buffered) -----------
// CTA 256 thr (8 warps 2x4), tile M=128 x N=128, k-chunk 32, smem stride 40.
#define GA(buf) ((buf) * 10240)
#define GB(buf) (20480 + (buf) * 10240)
#define G_SMEM 66048              // epilogue staging 128x129 f32 reuses buffer

__global__ __launch_bounds__(256) void qkv_gemm_mma(
    const float* __restrict__ X, const float* __restrict__ cosb,
    const float* __restrict__ sinb, const float* __restrict__ bias)
{
    extern __shared__ __align__(16) char smem[];
    const uint32_t sbase = smem_u32(smem);
    const int tid = threadIdx.x, lane = tid & 31, wid = tid >> 5;
    const int g = lane >> 2, t = lane & 3;
    const int wy = wid >> 2, wx = wid & 3;          // warp tile 64x32
    const int m0 = blockIdx.y * 128, n0 = blockIdx.x * 128;

    float acc[4][4][4];
#pragma unroll
    for (int i = 0; i < 4; i++)
#pragma unroll
        for (int j = 0; j < 4; j++)
#pragma unroll
            for (int q = 0; q < 4; q++) acc[i][j][q] = 0.f;

    const int arow = tid >> 1, aseg = (tid & 1) * 16;
    const int eo = arow * 40 + aseg;                 // element offset in tile
    const float* xrow = X + (size_t)(m0 + arow) * DIMV + aseg;
    const size_t gbrow = (size_t)(n0 + arow) * DIMV + aseg;

    float4 xv0, xv1, xv2, xv3;

    // Prologue: chunk 0 -> buffer 0
    {
        xv0 = *(const float4*)&xrow[0];
        xv1 = *(const float4*)&xrow[4];
        xv2 = *(const float4*)&xrow[8];
        xv3 = *(const float4*)&xrow[12];
        CP_ASYNC16(sbase + GB(0) + eo * 2,      (const char*)&g_WThi[gbrow]);
        CP_ASYNC16(sbase + GB(0) + eo * 2 + 16, (const char*)&g_WThi[gbrow + 8]);
        CP_COMMIT();
        *(uint4*)(smem + GA(0) + eo * 2) =
            make_uint4(packh(xv0.x, xv0.y), packh(xv0.z, xv0.w),
                       packh(xv1.x, xv1.y), packh(xv1.z, xv1.w));
        *(uint4*)(smem + GA(0) + eo * 2 + 16) =
            make_uint4(packh(xv2.x, xv2.y), packh(xv2.z, xv2.w),
                       packh(xv3.x, xv3.y), packh(xv3.z, xv3.w));
        CP_WAIT0();
        __syncthreads();
    }

    for (int c = 0; c < 48; c++) {
        const int buf = c & 1, nbuf = buf ^ 1;
        if (c + 1 < 48) {
            const float* xr = xrow + (c + 1) * 32;
            xv0 = *(const float4*)&xr[0];
            xv1 = *(const float4*)&xr[4];
            xv2 = *(const float4*)&xr[8];
            xv3 = *(const float4*)&xr[12];
            const size_t gb = gbrow + (c + 1) * 32;
            CP_ASYNC16(sbase + GB(nbuf) + eo * 2,      (const char*)&g_WThi[gb]);
            CP_ASYNC16(sbase + GB(nbuf) + eo * 2 + 16, (const char*)&g_WThi[gb + 8]);
            CP_COMMIT();
        }

        // MMA on buffer buf
#pragma unroll
        for (int kk = 0; kk < 32; kk += 16) {
            uint32_t aH[4][4];
#pragma unroll
            for (int mt = 0; mt < 4; mt++) {
                const int r0 = wy * 64 + mt * 16;
                const int c0 = kk + 2 * t, c1 = kk + 8 + 2 * t;
                aH[mt][0] = *(const uint32_t*)(smem + GA(buf) + ((r0 + g) * 40 + c0) * 2);
                aH[mt][1] = *(const uint32_t*)(smem + GA(buf) + ((r0 + g + 8) * 40 + c0) * 2);
                aH[mt][2] = *(const uint32_t*)(smem + GA(buf) + ((r0 + g) * 40 + c1) * 2);
                aH[mt][3] = *(const uint32_t*)(smem + GA(buf) + ((r0 + g + 8) * 40 + c1) * 2);
            }
#pragma unroll
            for (int nt = 0; nt < 4; nt++) {
                const int nr = wx * 32 + nt * 8 + g;
                const uint32_t bH0 = *(const uint32_t*)(smem + GB(buf) + (nr * 40 + kk + 2 * t) * 2);
                const uint32_t bH1 = *(const uint32_t*)(smem + GB(buf) + (nr * 40 + kk + 8 + 2 * t) * 2);
#pragma unroll
                for (int mt = 0; mt < 4; mt++)
                    mma16816(acc[mt][nt], aH[mt][0], aH[mt][1], aH[mt][2], aH[mt][3], bH0, bH1);
            }
        }

        if (c + 1 < 48) {
            *(uint4*)(smem + GA(nbuf) + eo * 2) =
                make_uint4(packh(xv0.x, xv0.y), packh(xv0.z, xv0.w),
                           packh(xv1.x, xv1.y), packh(xv1.z, xv1.w));
            *(uint4*)(smem + GA(nbuf) + eo * 2 + 16) =
                make_uint4(packh(xv2.x, xv2.y), packh(xv2.z, xv2.w),
                           packh(xv3.x, xv3.y), packh(xv3.z, xv3.w));
            CP_WAIT0();
        }
        __syncthreads();
    }

    // Stage accumulators (stride 129 f32)
    float* st = (float*)smem;
#pragma unroll
    for (int mt = 0; mt < 4; mt++)
#pragma unroll
        for (int nt = 0; nt < 4; nt++) {
            const int r = wy * 64 + mt * 16 + g;
            const int cx = wx * 32 + nt * 8 + 2 * t;
            st[r * 129 + cx]           = acc[mt][nt][0];
            st[r * 129 + cx + 1]       = acc[mt][nt][1];
            st[(r + 8) * 129 + cx]     = acc[mt][nt][2];
            st[(r + 8) * 129 + cx + 1] = acc[mt][nt][3];
        }
    __syncthreads();

    // Epilogue
    const int headSel = tid >> 7, row = tid & 127;
    const int m = m0 + row, b = m >> 12, s = m & (SEQ - 1);
    const int sec = n0 / DIMV, nloc = n0 % DIMV;
    const int h = nloc / HD + headSel;
    const int bh = b * NH + h;
    const int nb = n0 + headSel * 64;

    float v[64];
#pragma unroll
    for (int j = 0; j < 64; j++)
        v[j] = st[row * 129 + headSel * 64 + j] + bias[nb + j];

    if (sec < 2) {
        float ss = 0.f;
#pragma unroll
        for (int j = 0; j < 64; j++) ss = fmaf(v[j], v[j], ss);
        float rinv = rsqrtf(ss * (1.0f / 64.0f) + 1e-6f);
        if (sec == 0) rinv *= 0.18033688011f;   // fold 0.125*log2(e) into Q
        uint32_t ph[32];
#pragma unroll
        for (int i = 0; i < 32; i++) {
            const float cc = cosb[s * HD + 2 * i], sn = sinb[s * HD + 2 * i];
            const float x1 = v[2 * i] * rinv, x2 = v[2 * i + 1] * rinv;
            ph[i] = packh(fmaf(x1, cc, -x2 * sn), fmaf(x2, cc, x1 * sn));
        }
        unsigned short* dh = (sec == 0 ? g_Qhi : g_Khi) + ((size_t)bh * SEQ + s) * HD;
#pragma unroll
        for (int q = 0; q < 8; q++)
            *(uint4*)(dh + q * 8) = make_uint4(ph[4*q], ph[4*q+1], ph[4*q+2], ph[4*q+3]);
    } else {
        // V: transposed store [bh][d][s], fp16
#pragma unroll
        for (int d = 0; d < 64; d++)
            g_Vhi[((size_t)bh * HD + d) * SEQ + s] =
                __half_as_ushort(__float2half_rn(v[d]));
    }
}

// ---------------- Kernel 2: flash attention (fp16 HMMA, MUFU softmax) -------
// CTA 256 thr (8 warps x 16 q-rows), 64-key tiles, double-buffered cp.async.
#define AK(buf) ((buf) * 9216)
#define AV(buf) (18432 + (buf) * 9216)
#define A_SMEM 36864

__global__ __launch_bounds__(256, 2) void attn_mma(float* __restrict__ out) {
    extern __shared__ __align__(16) char smem[];
    const uint32_t sbase = smem_u32(smem);
    const int tid = threadIdx.x, lane = tid & 31, wid = tid >> 5;
    const int g = lane >> 2, t = lane & 3;
    const int bh = blockIdx.y, b = bh / NH, h = bh % NH;
    const int q0 = blockIdx.x * 128;

    // Q fragments in registers (fragment words are contiguous u32 in [s][d])
    uint32_t qf[4][4];
    {
        const size_t rbase = (size_t)bh * SEQ + q0 + wid * 16;
#pragma unroll
        for (int kq = 0; kq < 4; kq++) {
            const int c0 = kq * 16 + 2 * t, c1 = c0 + 8;
            qf[kq][0] = *(const uint32_t*)&g_Qhi[(rbase + g) * HD + c0];
            qf[kq][1] = *(const uint32_t*)&g_Qhi[(rbase + g + 8) * HD + c0];
            qf[kq][2] = *(const uint32_t*)&g_Qhi[(rbase + g) * HD + c1];
            qf[kq][3] = *(const uint32_t*)&g_Qhi[(rbase + g + 8) * HD + c1];
        }
    }

    float oacc[8][4];
#pragma unroll
    for (int i = 0; i < 8; i++)
#pragma unroll
        for (int j = 0; j < 4; j++) oacc[i][j] = 0.f;
    float rs0 = 0.f, rs1 = 0.f;

    const int krow = tid >> 2, kseg = (tid & 3) * 16;
    const uint32_t keo = (krow * 72 + kseg) * 2;

    // preload tile 0 into buffer 0
    {
        const size_t gk = ((size_t)bh * SEQ + krow) * HD + kseg;
        const size_t gv = ((size_t)bh * HD + krow) * SEQ + kseg;
        CP_ASYNC16(sbase + AK(0) + keo,      (const char*)&g_Khi[gk]);
        CP_ASYNC16(sbase + AK(0) + keo + 16, (const char*)&g_Khi[gk + 8]);
        CP_ASYNC16(sbase + AV(0) + keo,      (const char*)&g_Vhi[gv]);
        CP_ASYNC16(sbase + AV(0) + keo + 16, (const char*)&g_Vhi[gv + 8]);
        CP_COMMIT();
    }

    for (int kt = 0; kt < SEQ / 64; kt++) {
        CP_WAIT0();
        __syncthreads();
        if (kt + 1 < SEQ / 64) {
            const int nb2 = (kt + 1) & 1;
            const size_t gk = ((size_t)bh * SEQ + (kt + 1) * 64 + krow) * HD + kseg;
            const size_t gv = ((size_t)bh * HD + krow) * SEQ + (kt + 1) * 64 + kseg;
            CP_ASYNC16(sbase + AK(nb2) + keo,      (const char*)&g_Khi[gk]);
            CP_ASYNC16(sbase + AK(nb2) + keo + 16, (const char*)&g_Khi[gk + 8]);
            CP_ASYNC16(sbase + AV(nb2) + keo,      (const char*)&g_Vhi[gv]);
            CP_ASYNC16(sbase + AV(nb2) + keo + 16, (const char*)&g_Vhi[gv + 8]);
            CP_COMMIT();
        }
        const int buf = kt & 1;
        const char* kbase = smem + AK(buf);
        const char* vbase = smem + AV(buf);

        // S = Q K^T  (scores pre-scaled: Q carries 0.125*log2e)
        float sacc[8][4];
#pragma unroll
        for (int i = 0; i < 8; i++)
#pragma unroll
            for (int j = 0; j < 4; j++) sacc[i][j] = 0.f;

#pragma unroll
        for (int kq = 0; kq < 4; kq++) {
            const int c0 = kq * 16 + 2 * t, c1 = kq * 16 + 8 + 2 * t;
#pragma unroll
            for (int nt = 0; nt < 8; nt++) {
                const int nr = nt * 8 + g;
                const uint32_t bH0 = *(const uint32_t*)(kbase + (nr * 72 + c0) * 2);
                const uint32_t bH1 = *(const uint32_t*)(kbase + (nr * 72 + c1) * 2);
                mma16816(sacc[nt], qf[kq][0], qf[kq][1], qf[kq][2], qf[kq][3], bH0, bH1);
            }
        }

        // Softmax on MUFU (bounded scores: no max pass), repack P
        uint32_t paH[8][2];
#pragma unroll
        for (int nt = 0; nt < 8; nt++) {
            const float e0 = ex2(sacc[nt][0]);
            const float e1 = ex2(sacc[nt][1]);
            const float e2 = ex2(sacc[nt][2]);
            const float e3 = ex2(sacc[nt][3]);
            rs0 += e0 + e1;
            rs1 += e2 + e3;
            paH[nt][0] = packh(e0, e1);
            paH[nt][1] = packh(e2, e3);
        }

        // O += P V
#pragma unroll
        for (int k2 = 0; k2 < 4; k2++) {
            const uint32_t aH0 = paH[2*k2][0],   aH1 = paH[2*k2][1];
            const uint32_t aH2 = paH[2*k2+1][0], aH3 = paH[2*k2+1][1];
            const int c0 = k2 * 16 + 2 * t, c1 = k2 * 16 + 8 + 2 * t;
#pragma unroll
            for (int nt = 0; nt < 8; nt++) {
                const int nr = nt * 8 + g;
                const uint32_t bH0 = *(const uint32_t*)(vbase + (nr * 72 + c0) * 2);
                const uint32_t bH1 = *(const uint32_t*)(vbase + (nr * 72 + c1) * 2);
                mma16816(oacc[nt], aH0, aH1, aH2, aH3, bH0, bH1);
            }
        }
    }

    // Quad rowsum reduce, normalize, write
    rs0 += __shfl_xor_sync(0xffffffffu, rs0, 1);
    rs0 += __shfl_xor_sync(0xffffffffu, rs0, 2);
    rs1 += __shfl_xor_sync(0xffffffffu, rs1, 1);
    rs1 += __shfl_xor_sync(0xffffffffu, rs1, 2);
    const float inv0 = 1.0f / rs0, inv1 = 1.0f / rs1;

    const int s0 = q0 + wid * 16 + g, s1 = s0 + 8;
    float* o0 = &out[((size_t)b * SEQ + s0) * DIMV + h * HD];
    float* o1 = &out[((size_t)b * SEQ + s1) * DIMV + h * HD];
#pragma unroll
    for (int nt = 0; nt < 8; nt++) {
        const int cx = nt * 8 + 2 * t;
        *(float2*)(o0 + cx) = make_float2(oacc[nt][0] * inv0, oacc[nt][1] * inv0);
        *(float2*)(o1 + cx) = make_float2(oacc[nt][2] * inv1, oacc[nt][3] * inv1);
    }
}

// ---------------------------------------------------------------------------
extern "C" void kernel_launch(void* const* d_in, const int* in_sizes, int n_in,
                              void* d_out, int out_size) {
    const float* x    = (const float*)d_in[0];
    const float* cosb = (const float*)d_in[1];
    const float* sinb = (const float*)d_in[2];
    const float* w    = (const float*)d_in[3];
    const float* bq   = (const float*)d_in[4];

    cudaFuncSetAttribute(qkv_gemm_mma, cudaFuncAttributeMaxDynamicSharedMemorySize, G_SMEM);
    cudaFuncSetAttribute(attn_mma,     cudaFuncAttributeMaxDynamicSharedMemorySize, A_SMEM);

    wt_prep<<<dim3(N3 / 32, DIMV / 32), 256>>>(w);
    qkv_gemm_mma<<<dim3(N3 / 128, NT / 128), 256, G_SMEM>>>(x, cosb, sinb, bq);
    attn_mma<<<dim3(SEQ / 128, BHN), 256, A_SMEM>>>((float*)d_out);
}

// round 9
// speedup vs baseline: 6.8759x; 1.0413x over previous
#include <cuda_runtime.h>
#include <cuda_fp16.h>
#include <math.h>
#include <stdint.h>

#define SEQ   4096
#define BATCH 4
#define NH    24
#define HD    64
#define DIMV  1536
#define N3    4608
#define NT    16384
#define BHN   96

__device__ __align__(16) unsigned short g_WThi[(size_t)N3 * DIMV];    // [n][k] fp16
__device__ __align__(16) unsigned short g_Qhi[(size_t)BHN * SEQ * HD]; // [bh][s][d] (pre-scaled by 0.125*log2e)
__device__ __align__(16) unsigned short g_Khi[(size_t)BHN * SEQ * HD];
__device__ __align__(16) unsigned short g_Vhi[(size_t)BHN * HD * SEQ]; // [bh][d][s]

// ---------------- helpers ----------------
__device__ __forceinline__ void mma16816(float* c, uint32_t a0, uint32_t a1,
                                         uint32_t a2, uint32_t a3,
                                         uint32_t b0, uint32_t b1) {
    asm volatile(
        "mma.sync.aligned.m16n8k16.row.col.f32.f16.f16.f32 "
        "{%0,%1,%2,%3},{%4,%5,%6,%7},{%8,%9},{%0,%1,%2,%3};"
        : "+f"(c[0]), "+f"(c[1]), "+f"(c[2]), "+f"(c[3])
        : "r"(a0), "r"(a1), "r"(a2), "r"(a3), "r"(b0), "r"(b1));
}

#define LDSM4(r0, r1, r2, r3, addr) \
    asm volatile("ldmatrix.sync.aligned.m8n8.x4.shared.b16 {%0,%1,%2,%3}, [%4];" \
        : "=r"(r0), "=r"(r1), "=r"(r2), "=r"(r3) : "r"(addr))

__device__ __forceinline__ uint32_t packh(float a, float b) {
    __half2 h = __floats2half2_rn(a, b);
    return *(uint32_t*)&h;
}

// MUFU exp2 — separate pipe from FMA/tensor, 1 issue slot per exp
__device__ __forceinline__ float ex2(float y) {
    float r;
    asm("ex2.approx.f32 %0, %1;" : "=f"(r) : "f"(y));
    return r;
}

#define CP_ASYNC16(dst, src) \
    asm volatile("cp.async.ca.shared.global [%0], [%1], 16;" :: "r"(dst), "l"(src))
#define CP_COMMIT() asm volatile("cp.async.commit_group;" ::: "memory")
#define CP_WAIT0()  asm volatile("cp.async.wait_group 0;" ::: "memory")

__device__ __forceinline__ uint32_t smem_u32(const void* p) {
    uint32_t a;
    asm("{ .reg .u64 t; cvta.to.shared.u64 t, %1; cvt.u32.u64 %0, t; }" : "=r"(a) : "l"(p));
    return a;
}

// ---------------- Kernel 0: W transpose + fp16 ----------------
__global__ __launch_bounds__(256) void wt_prep(const float* __restrict__ W) {
    __shared__ float tile[32][33];
    const int n0 = blockIdx.x * 32, k0 = blockIdx.y * 32;
    const int tx = threadIdx.x & 31, ty = threadIdx.x >> 5;
    for (int r = ty; r < 32; r += 8)
        tile[r][tx] = W[(size_t)(k0 + r) * N3 + n0 + tx];
    __syncthreads();
    for (int r = ty; r < 32; r += 8) {
        g_WThi[(size_t)(n0 + r) * DIMV + k0 + tx] =
            __half_as_ushort(__float2half_rn(tile[tx][r]));
    }
}

// ---------------- Kernel 1: QKV GEMM (fp16 HMMA, double-buffered) -----------
// CTA 256 thr (8 warps 2x4), tile M=128 x N=128, k-chunk 32, smem stride 40.
#define GA(buf) ((buf) * 10240)
#define GB(buf) (20480 + (buf) * 10240)
#define G_SMEM 66048              // epilogue staging 128x129 f32 reuses buffer

__global__ __launch_bounds__(256) void qkv_gemm_mma(
    const float* __restrict__ X, const float* __restrict__ cosb,
    const float* __restrict__ sinb, const float* __restrict__ bias)
{
    extern __shared__ __align__(16) char smem[];
    const uint32_t sbase = smem_u32(smem);
    const int tid = threadIdx.x, lane = tid & 31, wid = tid >> 5;
    const int g = lane >> 2, t = lane & 3;
    const int wy = wid >> 2, wx = wid & 3;          // warp tile 64x32
    const int m0 = blockIdx.y * 128, n0 = blockIdx.x * 128;

    float acc[4][4][4];
#pragma unroll
    for (int i = 0; i < 4; i++)
#pragma unroll
        for (int j = 0; j < 4; j++)
#pragma unroll
            for (int q = 0; q < 4; q++) acc[i][j][q] = 0.f;

    const int arow = tid >> 1, aseg = (tid & 1) * 16;
    const int eo = arow * 40 + aseg;                 // element offset in tile
    const float* xrow = X + (size_t)(m0 + arow) * DIMV + aseg;
    const size_t gbrow = (size_t)(n0 + arow) * DIMV + aseg;

    float4 xv0, xv1, xv2, xv3;

    // Prologue: chunk 0 -> buffer 0
    {
        xv0 = *(const float4*)&xrow[0];
        xv1 = *(const float4*)&xrow[4];
        xv2 = *(const float4*)&xrow[8];
        xv3 = *(const float4*)&xrow[12];
        CP_ASYNC16(sbase + GB(0) + eo * 2,      (const char*)&g_WThi[gbrow]);
        CP_ASYNC16(sbase + GB(0) + eo * 2 + 16, (const char*)&g_WThi[gbrow + 8]);
        CP_COMMIT();
        *(uint4*)(smem + GA(0) + eo * 2) =
            make_uint4(packh(xv0.x, xv0.y), packh(xv0.z, xv0.w),
                       packh(xv1.x, xv1.y), packh(xv1.z, xv1.w));
        *(uint4*)(smem + GA(0) + eo * 2 + 16) =
            make_uint4(packh(xv2.x, xv2.y), packh(xv2.z, xv2.w),
                       packh(xv3.x, xv3.y), packh(xv3.z, xv3.w));
        CP_WAIT0();
        __syncthreads();
    }

    for (int c = 0; c < 48; c++) {
        const int buf = c & 1, nbuf = buf ^ 1;
        if (c + 1 < 48) {
            const float* xr = xrow + (c + 1) * 32;
            xv0 = *(const float4*)&xr[0];
            xv1 = *(const float4*)&xr[4];
            xv2 = *(const float4*)&xr[8];
            xv3 = *(const float4*)&xr[12];
            const size_t gb = gbrow + (c + 1) * 32;
            CP_ASYNC16(sbase + GB(nbuf) + eo * 2,      (const char*)&g_WThi[gb]);
            CP_ASYNC16(sbase + GB(nbuf) + eo * 2 + 16, (const char*)&g_WThi[gb + 8]);
            CP_COMMIT();
        }

        // MMA on buffer buf
#pragma unroll
        for (int kk = 0; kk < 32; kk += 16) {
            uint32_t aH[4][4];
#pragma unroll
            for (int mt = 0; mt < 4; mt++) {
                const int r0 = wy * 64 + mt * 16;
                const int c0 = kk + 2 * t, c1 = kk + 8 + 2 * t;
                aH[mt][0] = *(const uint32_t*)(smem + GA(buf) + ((r0 + g) * 40 + c0) * 2);
                aH[mt][1] = *(const uint32_t*)(smem + GA(buf) + ((r0 + g + 8) * 40 + c0) * 2);
                aH[mt][2] = *(const uint32_t*)(smem + GA(buf) + ((r0 + g) * 40 + c1) * 2);
                aH[mt][3] = *(const uint32_t*)(smem + GA(buf) + ((r0 + g + 8) * 40 + c1) * 2);
            }
#pragma unroll
            for (int nt = 0; nt < 4; nt++) {
                const int nr = wx * 32 + nt * 8 + g;
                const uint32_t bH0 = *(const uint32_t*)(smem + GB(buf) + (nr * 40 + kk + 2 * t) * 2);
                const uint32_t bH1 = *(const uint32_t*)(smem + GB(buf) + (nr * 40 + kk + 8 + 2 * t) * 2);
#pragma unroll
                for (int mt = 0; mt < 4; mt++)
                    mma16816(acc[mt][nt], aH[mt][0], aH[mt][1], aH[mt][2], aH[mt][3], bH0, bH1);
            }
        }

        if (c + 1 < 48) {
            *(uint4*)(smem + GA(nbuf) + eo * 2) =
                make_uint4(packh(xv0.x, xv0.y), packh(xv0.z, xv0.w),
                           packh(xv1.x, xv1.y), packh(xv1.z, xv1.w));
            *(uint4*)(smem + GA(nbuf) + eo * 2 + 16) =
                make_uint4(packh(xv2.x, xv2.y), packh(xv2.z, xv2.w),
                           packh(xv3.x, xv3.y), packh(xv3.z, xv3.w));
            CP_WAIT0();
        }
        __syncthreads();
    }

    // Stage accumulators (stride 129 f32)
    float* st = (float*)smem;
#pragma unroll
    for (int mt = 0; mt < 4; mt++)
#pragma unroll
        for (int nt = 0; nt < 4; nt++) {
            const int r = wy * 64 + mt * 16 + g;
            const int cx = wx * 32 + nt * 8 + 2 * t;
            st[r * 129 + cx]           = acc[mt][nt][0];
            st[r * 129 + cx + 1]       = acc[mt][nt][1];
            st[(r + 8) * 129 + cx]     = acc[mt][nt][2];
            st[(r + 8) * 129 + cx + 1] = acc[mt][nt][3];
        }
    __syncthreads();

    // Epilogue
    const int headSel = tid >> 7, row = tid & 127;
    const int m = m0 + row, b = m >> 12, s = m & (SEQ - 1);
    const int sec = n0 / DIMV, nloc = n0 % DIMV;
    const int h = nloc / HD + headSel;
    const int bh = b * NH + h;
    const int nb = n0 + headSel * 64;

    float v[64];
#pragma unroll
    for (int j = 0; j < 64; j++)
        v[j] = st[row * 129 + headSel * 64 + j] + bias[nb + j];

    if (sec < 2) {
        float ss = 0.f;
#pragma unroll
        for (int j = 0; j < 64; j++) ss = fmaf(v[j], v[j], ss);
        float rinv = rsqrtf(ss * (1.0f / 64.0f) + 1e-6f);
        if (sec == 0) rinv *= 0.18033688011f;   // fold 0.125*log2(e) into Q
        uint32_t ph[32];
#pragma unroll
        for (int i = 0; i < 32; i++) {
            const float cc = cosb[s * HD + 2 * i], sn = sinb[s * HD + 2 * i];
            const float x1 = v[2 * i] * rinv, x2 = v[2 * i + 1] * rinv;
            ph[i] = packh(fmaf(x1, cc, -x2 * sn), fmaf(x2, cc, x1 * sn));
        }
        unsigned short* dh = (sec == 0 ? g_Qhi : g_Khi) + ((size_t)bh * SEQ + s) * HD;
#pragma unroll
        for (int q = 0; q < 8; q++)
            *(uint4*)(dh + q * 8) = make_uint4(ph[4*q], ph[4*q+1], ph[4*q+2], ph[4*q+3]);
    } else {
        // V: transposed store [bh][d][s], fp16
#pragma unroll
        for (int d = 0; d < 64; d++)
            g_Vhi[((size_t)bh * HD + d) * SEQ + s] =
                __half_as_ushort(__float2half_rn(v[d]));
    }
}

// ---------------- Kernel 2: flash attention (fp16 HMMA + ldmatrix) ----------
// CTA 256 thr (8 warps x 16 q-rows), 64-key tiles, double-buffered cp.async.
#define AK(buf) ((buf) * 9216)
#define AV(buf) (18432 + (buf) * 9216)
#define A_SMEM 36864

__global__ __launch_bounds__(256, 2) void attn_mma(float* __restrict__ out) {
    extern __shared__ __align__(16) char smem[];
    const uint32_t sbase = smem_u32(smem);
    const int tid = threadIdx.x, lane = tid & 31, wid = tid >> 5;
    const int g = lane >> 2, t = lane & 3;
    const int bh = blockIdx.y, b = bh / NH, h = bh % NH;
    const int q0 = blockIdx.x * 128;

    // ldmatrix lane offset: lanes 0-7 -> (row mrow, col 0), 8-15 -> (mrow, 8),
    // 16-23 -> (8+mrow, 0), 24-31 -> (8+mrow, 8)   [within a 16x16 block]
    const int mrow = lane & 7, msel = lane >> 3;
    const uint32_t laneoff = (((msel >> 1) * 8 + mrow) * 72 + (msel & 1) * 8) * 2;

    // Q fragments in registers (fragment words are contiguous u32 in [s][d])
    uint32_t qf[4][4];
    {
        const size_t rbase = (size_t)bh * SEQ + q0 + wid * 16;
#pragma unroll
        for (int kq = 0; kq < 4; kq++) {
            const int c0 = kq * 16 + 2 * t, c1 = c0 + 8;
            qf[kq][0] = *(const uint32_t*)&g_Qhi[(rbase + g) * HD + c0];
            qf[kq][1] = *(const uint32_t*)&g_Qhi[(rbase + g + 8) * HD + c0];
            qf[kq][2] = *(const uint32_t*)&g_Qhi[(rbase + g) * HD + c1];
            qf[kq][3] = *(const uint32_t*)&g_Qhi[(rbase + g + 8) * HD + c1];
        }
    }

    float oacc[8][4];
#pragma unroll
    for (int i = 0; i < 8; i++)
#pragma unroll
        for (int j = 0; j < 4; j++) oacc[i][j] = 0.f;
    float rs0 = 0.f, rs1 = 0.f;

    const int krow = tid >> 2, kseg = (tid & 3) * 16;
    const uint32_t keo = (krow * 72 + kseg) * 2;

    // preload tile 0 into buffer 0
    {
        const size_t gk = ((size_t)bh * SEQ + krow) * HD + kseg;
        const size_t gv = ((size_t)bh * HD + krow) * SEQ + kseg;
        CP_ASYNC16(sbase + AK(0) + keo,      (const char*)&g_Khi[gk]);
        CP_ASYNC16(sbase + AK(0) + keo + 16, (const char*)&g_Khi[gk + 8]);
        CP_ASYNC16(sbase + AV(0) + keo,      (const char*)&g_Vhi[gv]);
        CP_ASYNC16(sbase + AV(0) + keo + 16, (const char*)&g_Vhi[gv + 8]);
        CP_COMMIT();
    }

    for (int kt = 0; kt < SEQ / 64; kt++) {
        CP_WAIT0();
        __syncthreads();
        if (kt + 1 < SEQ / 64) {
            const int nb2 = (kt + 1) & 1;
            const size_t gk = ((size_t)bh * SEQ + (kt + 1) * 64 + krow) * HD + kseg;
            const size_t gv = ((size_t)bh * HD + krow) * SEQ + (kt + 1) * 64 + kseg;
            CP_ASYNC16(sbase + AK(nb2) + keo,      (const char*)&g_Khi[gk]);
            CP_ASYNC16(sbase + AK(nb2) + keo + 16, (const char*)&g_Khi[gk + 8]);
            CP_ASYNC16(sbase + AV(nb2) + keo,      (const char*)&g_Vhi[gv]);
            CP_ASYNC16(sbase + AV(nb2) + keo + 16, (const char*)&g_Vhi[gv + 8]);
            CP_COMMIT();
        }
        const int buf = kt & 1;
        const uint32_t kab = sbase + AK(buf) + laneoff;   // ldmatrix base (K)
        const uint32_t vab = sbase + AV(buf) + laneoff;   // ldmatrix base (V)

        // S = Q K^T  (scores pre-scaled: Q carries 0.125*log2e)
        float sacc[8][4];
#pragma unroll
        for (int i = 0; i < 8; i++)
#pragma unroll
            for (int j = 0; j < 4; j++) sacc[i][j] = 0.f;

#pragma unroll
        for (int kq = 0; kq < 4; kq++) {
#pragma unroll
            for (int np = 0; np < 4; np++) {
                uint32_t b0, b1, b2, b3;
                LDSM4(b0, b1, b2, b3, kab + np * 2304 + kq * 32);
                mma16816(sacc[2*np],   qf[kq][0], qf[kq][1], qf[kq][2], qf[kq][3], b0, b1);
                mma16816(sacc[2*np+1], qf[kq][0], qf[kq][1], qf[kq][2], qf[kq][3], b2, b3);
            }
        }

        // Softmax on MUFU (bounded scores: no max pass), repack P
        uint32_t paH[8][2];
#pragma unroll
        for (int nt = 0; nt < 8; nt++) {
            const float e0 = ex2(sacc[nt][0]);
            const float e1 = ex2(sacc[nt][1]);
            const float e2 = ex2(sacc[nt][2]);
            const float e3 = ex2(sacc[nt][3]);
            rs0 += e0 + e1;
            rs1 += e2 + e3;
            paH[nt][0] = packh(e0, e1);
            paH[nt][1] = packh(e2, e3);
        }

        // O += P V
#pragma unroll
        for (int k2 = 0; k2 < 4; k2++) {
            const uint32_t aH0 = paH[2*k2][0],   aH1 = paH[2*k2][1];
            const uint32_t aH2 = paH[2*k2+1][0], aH3 = paH[2*k2+1][1];
#pragma unroll
            for (int np = 0; np < 4; np++) {
                uint32_t b0, b1, b2, b3;
                LDSM4(b0, b1, b2, b3, vab + np * 2304 + k2 * 32);
                mma16816(oacc[2*np],   aH0, aH1, aH2, aH3, b0, b1);
                mma16816(oacc[2*np+1], aH0, aH1, aH2, aH3, b2, b3);
            }
        }
    }

    // Quad rowsum reduce, normalize, write
    rs0 += __shfl_xor_sync(0xffffffffu, rs0, 1);
    rs0 += __shfl_xor_sync(0xffffffffu, rs0, 2);
    rs1 += __shfl_xor_sync(0xffffffffu, rs1, 1);
    rs1 += __shfl_xor_sync(0xffffffffu, rs1, 2);
    const float inv0 = 1.0f / rs0, inv1 = 1.0f / rs1;

    const int s0 = q0 + wid * 16 + g, s1 = s0 + 8;
    float* o0 = &out[((size_t)b * SEQ + s0) * DIMV + h * HD];
    float* o1 = &out[((size_t)b * SEQ + s1) * DIMV + h * HD];
#pragma unroll
    for (int nt = 0; nt < 8; nt++) {
        const int cx = nt * 8 + 2 * t;
        *(float2*)(o0 + cx) = make_float2(oacc[nt][0] * inv0, oacc[nt][1] * inv0);
        *(float2*)(o1 + cx) = make_float2(oacc[nt][2] * inv1, oacc[nt][3] * inv1);
    }
}

// ---------------------------------------------------------------------------
extern "C" void kernel_launch(void* const* d_in, const int* in_sizes, int n_in,
                              void* d_out, int out_size) {
    const float* x    = (const float*)d_in[0];
    const float* cosb = (const float*)d_in[1];
    const float* sinb = (const float*)d_in[2];
    const float* w    = (const float*)d_in[3];
    const float* bq   = (const float*)d_in[4];

    cudaFuncSetAttribute(qkv_gemm_mma, cudaFuncAttributeMaxDynamicSharedMemorySize, G_SMEM);
    cudaFuncSetAttribute(attn_mma,     cudaFuncAttributeMaxDynamicSharedMemorySize, A_SMEM);

    wt_prep<<<dim3(N3 / 32, DIMV / 32), 256>>>(w);
    qkv_gemm_mma<<<dim3(N3 / 128, NT / 128), 256, G_SMEM>>>(x, cosb, sinb, bq);
    attn_mma<<<dim3(SEQ / 128, BHN), 256, A_SMEM>>>((float*)d_out);
}

// round 10
// speedup vs baseline: 8.0989x; 1.1779x over previous
#include <cuda_runtime.h>
#include <cuda_fp16.h>
#include <math.h>
#include <stdint.h>

#define SEQ   4096
#define BATCH 4
#define NH    24
#define HD    64
#define DIMV  1536
#define N3    4608
#define NT    16384
#define BHN   96

__device__ __align__(16) unsigned short g_X16 [(size_t)NT * DIMV];    // [m][k] fp16
__device__ __align__(16) unsigned short g_WThi[(size_t)N3 * DIMV];    // [n][k] fp16
__device__ __align__(16) unsigned short g_Qhi[(size_t)BHN * SEQ * HD]; // [bh][s][d] (pre-scaled by 0.125*log2e)
__device__ __align__(16) unsigned short g_Khi[(size_t)BHN * SEQ * HD];
__device__ __align__(16) unsigned short g_Vhi[(size_t)BHN * HD * SEQ]; // [bh][d][s]

// ---------------- helpers ----------------
__device__ __forceinline__ void mma16816(float* c, uint32_t a0, uint32_t a1,
                                         uint32_t a2, uint32_t a3,
                                         uint32_t b0, uint32_t b1) {
    asm volatile(
        "mma.sync.aligned.m16n8k16.row.col.f32.f16.f16.f32 "
        "{%0,%1,%2,%3},{%4,%5,%6,%7},{%8,%9},{%0,%1,%2,%3};"
        : "+f"(c[0]), "+f"(c[1]), "+f"(c[2]), "+f"(c[3])
        : "r"(a0), "r"(a1), "r"(a2), "r"(a3), "r"(b0), "r"(b1));
}

#define LDSM4(r0, r1, r2, r3, addr) \
    asm volatile("ldmatrix.sync.aligned.m8n8.x4.shared.b16 {%0,%1,%2,%3}, [%4];" \
        : "=r"(r0), "=r"(r1), "=r"(r2), "=r"(r3) : "r"(addr))

__device__ __forceinline__ uint32_t packh(float a, float b) {
    __half2 h = __floats2half2_rn(a, b);
    return *(uint32_t*)&h;
}

// MUFU exp2 — separate pipe from FMA/tensor, 1 issue slot per exp
__device__ __forceinline__ float ex2(float y) {
    float r;
    asm("ex2.approx.f32 %0, %1;" : "=f"(r) : "f"(y));
    return r;
}

#define CP_ASYNC16(dst, src) \
    asm volatile("cp.async.ca.shared.global [%0], [%1], 16;" :: "r"(dst), "l"(src))
#define CP_COMMIT() asm volatile("cp.async.commit_group;" ::: "memory")
#define CP_WAIT0()  asm volatile("cp.async.wait_group 0;" ::: "memory")

__device__ __forceinline__ uint32_t smem_u32(const void* p) {
    uint32_t a;
    asm("{ .reg .u64 t; cvta.to.shared.u64 t, %1; cvt.u32.u64 %0, t; }" : "=r"(a) : "l"(p));
    return a;
}

// ---------------- Kernel 0a: X -> fp16 (once; kills 36x reconvert) ----------
__global__ __launch_bounds__(256) void x16_prep(const float* __restrict__ X) {
    const size_t i = ((size_t)blockIdx.x * 256 + threadIdx.x) * 8;
    float4 v0 = *(const float4*)&X[i];
    float4 v1 = *(const float4*)&X[i + 4];
    *(uint4*)&g_X16[i] = make_uint4(packh(v0.x, v0.y), packh(v0.z, v0.w),
                                    packh(v1.x, v1.y), packh(v1.z, v1.w));
}

// ---------------- Kernel 0b: W transpose + fp16 ----------------
__global__ __launch_bounds__(256) void wt_prep(const float* __restrict__ W) {
    __shared__ float tile[32][33];
    const int n0 = blockIdx.x * 32, k0 = blockIdx.y * 32;
    const int tx = threadIdx.x & 31, ty = threadIdx.x >> 5;
    for (int r = ty; r < 32; r += 8)
        tile[r][tx] = W[(size_t)(k0 + r) * N3 + n0 + tx];
    __syncthreads();
    for (int r = ty; r < 32; r += 8) {
        g_WThi[(size_t)(n0 + r) * DIMV + k0 + tx] =
            __half_as_ushort(__float2half_rn(tile[tx][r]));
    }
}

// ---------------- Kernel 1: QKV GEMM (fp16 HMMA, cp.async + ldmatrix) -------
// CTA 256 thr (8 warps 2x4), tile M=128 x N=128, k-chunk 32, smem stride 40.
#define GA(buf) ((buf) * 10240)
#define GB(buf) (20480 + (buf) * 10240)
#define G_SMEM 66048              // epilogue staging 128x129 f32 reuses buffer

__global__ __launch_bounds__(256, 2) void qkv_gemm_mma(
    const float* __restrict__ cosb, const float* __restrict__ sinb,
    const float* __restrict__ bias)
{
    extern __shared__ __align__(16) char smem[];
    const uint32_t sbase = smem_u32(smem);
    const int tid = threadIdx.x, lane = tid & 31, wid = tid >> 5;
    const int g = lane >> 2, t = lane & 3;
    const int wy = wid >> 2, wx = wid & 3;          // warp tile 64x32
    const int m0 = blockIdx.y * 128, n0 = blockIdx.x * 128;

    float acc[4][4][4];
#pragma unroll
    for (int i = 0; i < 4; i++)
#pragma unroll
        for (int j = 0; j < 4; j++)
#pragma unroll
            for (int q = 0; q < 4; q++) acc[i][j][q] = 0.f;

    const int arow = tid >> 1, aseg = (tid & 1) * 16;
    const int eo = arow * 40 + aseg;                 // element offset in tile
    const unsigned short* x16row = g_X16 + (size_t)(m0 + arow) * DIMV + aseg;
    const unsigned short* wrow   = g_WThi + (size_t)(n0 + arow) * DIMV + aseg;

    // ldmatrix lane offsets (A: a0..a3 = m0..m3 -> row += (msel&1)*8, col += (msel>>1)*8)
    // (B: attention-verified map        -> row += (msel>>1)*8, col += (msel&1)*8)
    const int mrow = lane & 7, msel = lane >> 3;
    const uint32_t laneA = (((msel & 1) * 8 + mrow) * 40 + (msel >> 1) * 8) * 2;
    const uint32_t laneB = (((msel >> 1) * 8 + mrow) * 40 + (msel & 1) * 8) * 2;

    // Prologue: chunk 0 -> buffer 0
    CP_ASYNC16(sbase + GA(0) + eo * 2,      (const char*)x16row);
    CP_ASYNC16(sbase + GA(0) + eo * 2 + 16, (const char*)(x16row + 8));
    CP_ASYNC16(sbase + GB(0) + eo * 2,      (const char*)wrow);
    CP_ASYNC16(sbase + GB(0) + eo * 2 + 16, (const char*)(wrow + 8));
    CP_COMMIT();
    CP_WAIT0();
    __syncthreads();

    for (int c = 0; c < 48; c++) {
        const int buf = c & 1, nbuf = buf ^ 1;
        if (c + 1 < 48) {
            const unsigned short* xa = x16row + (c + 1) * 32;
            const unsigned short* wb = wrow + (c + 1) * 32;
            CP_ASYNC16(sbase + GA(nbuf) + eo * 2,      (const char*)xa);
            CP_ASYNC16(sbase + GA(nbuf) + eo * 2 + 16, (const char*)(xa + 8));
            CP_ASYNC16(sbase + GB(nbuf) + eo * 2,      (const char*)wb);
            CP_ASYNC16(sbase + GB(nbuf) + eo * 2 + 16, (const char*)(wb + 8));
            CP_COMMIT();
        }

        // MMA on buffer buf
#pragma unroll
        for (int kk = 0; kk < 32; kk += 16) {
            uint32_t aH[4][4], bf[2][4];
#pragma unroll
            for (int mt = 0; mt < 4; mt++)
                LDSM4(aH[mt][0], aH[mt][1], aH[mt][2], aH[mt][3],
                      sbase + GA(buf) + laneA + ((wy * 64 + mt * 16) * 40 + kk) * 2);
#pragma unroll
            for (int hf = 0; hf < 2; hf++)
                LDSM4(bf[hf][0], bf[hf][1], bf[hf][2], bf[hf][3],
                      sbase + GB(buf) + laneB + ((wx * 32 + hf * 16) * 40 + kk) * 2);
#pragma unroll
            for (int nt = 0; nt < 4; nt++) {
                const uint32_t b0 = bf[nt >> 1][(nt & 1) * 2];
                const uint32_t b1 = bf[nt >> 1][(nt & 1) * 2 + 1];
#pragma unroll
                for (int mt = 0; mt < 4; mt++)
                    mma16816(acc[mt][nt], aH[mt][0], aH[mt][1], aH[mt][2], aH[mt][3], b0, b1);
            }
        }

        if (c + 1 < 48) CP_WAIT0();
        __syncthreads();
    }

    // Stage accumulators (stride 129 f32)
    float* st = (float*)smem;
#pragma unroll
    for (int mt = 0; mt < 4; mt++)
#pragma unroll
        for (int nt = 0; nt < 4; nt++) {
            const int r = wy * 64 + mt * 16 + g;
            const int cx = wx * 32 + nt * 8 + 2 * t;
            st[r * 129 + cx]           = acc[mt][nt][0];
            st[r * 129 + cx + 1]       = acc[mt][nt][1];
            st[(r + 8) * 129 + cx]     = acc[mt][nt][2];
            st[(r + 8) * 129 + cx + 1] = acc[mt][nt][3];
        }
    __syncthreads();

    // Epilogue
    const int headSel = tid >> 7, row = tid & 127;
    const int m = m0 + row, b = m >> 12, s = m & (SEQ - 1);
    const int sec = n0 / DIMV, nloc = n0 % DIMV;
    const int h = nloc / HD + headSel;
    const int bh = b * NH + h;
    const int nb = n0 + headSel * 64;

    float v[64];
#pragma unroll
    for (int j = 0; j < 64; j++)
        v[j] = st[row * 129 + headSel * 64 + j] + bias[nb + j];

    if (sec < 2) {
        float ss = 0.f;
#pragma unroll
        for (int j = 0; j < 64; j++) ss = fmaf(v[j], v[j], ss);
        float rinv = rsqrtf(ss * (1.0f / 64.0f) + 1e-6f);
        if (sec == 0) rinv *= 0.18033688011f;   // fold 0.125*log2(e) into Q
        uint32_t ph[32];
#pragma unroll
        for (int i = 0; i < 32; i++) {
            const float cc = cosb[s * HD + 2 * i], sn = sinb[s * HD + 2 * i];
            const float x1 = v[2 * i] * rinv, x2 = v[2 * i + 1] * rinv;
            ph[i] = packh(fmaf(x1, cc, -x2 * sn), fmaf(x2, cc, x1 * sn));
        }
        unsigned short* dh = (sec == 0 ? g_Qhi : g_Khi) + ((size_t)bh * SEQ + s) * HD;
#pragma unroll
        for (int q = 0; q < 8; q++)
            *(uint4*)(dh + q * 8) = make_uint4(ph[4*q], ph[4*q+1], ph[4*q+2], ph[4*q+3]);
    } else {
        // V: transposed store [bh][d][s], fp16
#pragma unroll
        for (int d = 0; d < 64; d++)
            g_Vhi[((size_t)bh * HD + d) * SEQ + s] =
                __half_as_ushort(__float2half_rn(v[d]));
    }
}

// ---------------- Kernel 2: flash attention (fp16 HMMA + ldmatrix) ----------
// CTA 256 thr (8 warps x 16 q-rows), 64-key tiles, double-buffered cp.async.
#define AK(buf) ((buf) * 9216)
#define AV(buf) (18432 + (buf) * 9216)
#define A_SMEM 36864

__global__ __launch_bounds__(256, 2) void attn_mma(float* __restrict__ out) {
    extern __shared__ __align__(16) char smem[];
    const uint32_t sbase = smem_u32(smem);
    const int tid = threadIdx.x, lane = tid & 31, wid = tid >> 5;
    const int g = lane >> 2, t = lane & 3;
    const int bh = blockIdx.y, b = bh / NH, h = bh % NH;
    const int q0 = blockIdx.x * 128;

    const int mrow = lane & 7, msel = lane >> 3;
    const uint32_t laneoff = (((msel >> 1) * 8 + mrow) * 72 + (msel & 1) * 8) * 2;

    // Q fragments in registers (fragment words are contiguous u32 in [s][d])
    uint32_t qf[4][4];
    {
        const size_t rbase = (size_t)bh * SEQ + q0 + wid * 16;
#pragma unroll
        for (int kq = 0; kq < 4; kq++) {
            const int c0 = kq * 16 + 2 * t, c1 = c0 + 8;
            qf[kq][0] = *(const uint32_t*)&g_Qhi[(rbase + g) * HD + c0];
            qf[kq][1] = *(const uint32_t*)&g_Qhi[(rbase + g + 8) * HD + c0];
            qf[kq][2] = *(const uint32_t*)&g_Qhi[(rbase + g) * HD + c1];
            qf[kq][3] = *(const uint32_t*)&g_Qhi[(rbase + g + 8) * HD + c1];
        }
    }

    float oacc[8][4];
#pragma unroll
    for (int i = 0; i < 8; i++)
#pragma unroll
        for (int j = 0; j < 4; j++) oacc[i][j] = 0.f;
    float rs0 = 0.f, rs1 = 0.f;

    const int krow = tid >> 2, kseg = (tid & 3) * 16;
    const uint32_t keo = (krow * 72 + kseg) * 2;

    // preload tile 0 into buffer 0
    {
        const size_t gk = ((size_t)bh * SEQ + krow) * HD + kseg;
        const size_t gv = ((size_t)bh * HD + krow) * SEQ + kseg;
        CP_ASYNC16(sbase + AK(0) + keo,      (const char*)&g_Khi[gk]);
        CP_ASYNC16(sbase + AK(0) + keo + 16, (const char*)&g_Khi[gk + 8]);
        CP_ASYNC16(sbase + AV(0) + keo,      (const char*)&g_Vhi[gv]);
        CP_ASYNC16(sbase + AV(0) + keo + 16, (const char*)&g_Vhi[gv + 8]);
        CP_COMMIT();
    }

    for (int kt = 0; kt < SEQ / 64; kt++) {
        CP_WAIT0();
        __syncthreads();
        if (kt + 1 < SEQ / 64) {
            const int nb2 = (kt + 1) & 1;
            const size_t gk = ((size_t)bh * SEQ + (kt + 1) * 64 + krow) * HD + kseg;
            const size_t gv = ((size_t)bh * HD + krow) * SEQ + (kt + 1) * 64 + kseg;
            CP_ASYNC16(sbase + AK(nb2) + keo,      (const char*)&g_Khi[gk]);
            CP_ASYNC16(sbase + AK(nb2) + keo + 16, (const char*)&g_Khi[gk + 8]);
            CP_ASYNC16(sbase + AV(nb2) + keo,      (const char*)&g_Vhi[gv]);
            CP_ASYNC16(sbase + AV(nb2) + keo + 16, (const char*)&g_Vhi[gv + 8]);
            CP_COMMIT();
        }
        const int buf = kt & 1;
        const uint32_t kab = sbase + AK(buf) + laneoff;   // ldmatrix base (K)
        const uint32_t vab = sbase + AV(buf) + laneoff;   // ldmatrix base (V)

        // S = Q K^T  (scores pre-scaled: Q carries 0.125*log2e)
        float sacc[8][4];
#pragma unroll
        for (int i = 0; i < 8; i++)
#pragma unroll
            for (int j = 0; j < 4; j++) sacc[i][j] = 0.f;

#pragma unroll
        for (int kq = 0; kq < 4; kq++) {
#pragma unroll
            for (int np = 0; np < 4; np++) {
                uint32_t b0, b1, b2, b3;
                LDSM4(b0, b1, b2, b3, kab + np * 2304 + kq * 32);
                mma16816(sacc[2*np],   qf[kq][0], qf[kq][1], qf[kq][2], qf[kq][3], b0, b1);
                mma16816(sacc[2*np+1], qf[kq][0], qf[kq][1], qf[kq][2], qf[kq][3], b2, b3);
            }
        }

        // Softmax on MUFU (bounded scores: no max pass), repack P
        uint32_t paH[8][2];
#pragma unroll
        for (int nt = 0; nt < 8; nt++) {
            const float e0 = ex2(sacc[nt][0]);
            const float e1 = ex2(sacc[nt][1]);
            const float e2 = ex2(sacc[nt][2]);
            const float e3 = ex2(sacc[nt][3]);
            rs0 += e0 + e1;
            rs1 += e2 + e3;
            paH[nt][0] = packh(e0, e1);
            paH[nt][1] = packh(e2, e3);
        }

        // O += P V
#pragma unroll
        for (int k2 = 0; k2 < 4; k2++) {
            const uint32_t aH0 = paH[2*k2][0],   aH1 = paH[2*k2][1];
            const uint32_t aH2 = paH[2*k2+1][0], aH3 = paH[2*k2+1][1];
#pragma unroll
            for (int np = 0; np < 4; np++) {
                uint32_t b0, b1, b2, b3;
                LDSM4(b0, b1, b2, b3, vab + np * 2304 + k2 * 32);
                mma16816(oacc[2*np],   aH0, aH1, aH2, aH3, b0, b1);
                mma16816(oacc[2*np+1], aH0, aH1, aH2, aH3, b2, b3);
            }
        }
    }

    // Quad rowsum reduce, normalize, write
    rs0 += __shfl_xor_sync(0xffffffffu, rs0, 1);
    rs0 += __shfl_xor_sync(0xffffffffu, rs0, 2);
    rs1 += __shfl_xor_sync(0xffffffffu, rs1, 1);
    rs1 += __shfl_xor_sync(0xffffffffu, rs1, 2);
    const float inv0 = 1.0f / rs0, inv1 = 1.0f / rs1;

    const int s0 = q0 + wid * 16 + g, s1 = s0 + 8;
    float* o0 = &out[((size_t)b * SEQ + s0) * DIMV + h * HD];
    float* o1 = &out[((size_t)b * SEQ + s1) * DIMV + h * HD];
#pragma unroll
    for (int nt = 0; nt < 8; nt++) {
        const int cx = nt * 8 + 2 * t;
        *(float2*)(o0 + cx) = make_float2(oacc[nt][0] * inv0, oacc[nt][1] * inv0);
        *(float2*)(o1 + cx) = make_float2(oacc[nt][2] * inv1, oacc[nt][3] * inv1);
    }
}

// ---------------------------------------------------------------------------
extern "C" void kernel_launch(void* const* d_in, const int* in_sizes, int n_in,
                              void* d_out, int out_size) {
    const float* x    = (const float*)d_in[0];
    const float* cosb = (const float*)d_in[1];
    const float* sinb = (const float*)d_in[2];
    const float* w    = (const float*)d_in[3];
    const float* bq   = (const float*)d_in[4];

    cudaFuncSetAttribute(qkv_gemm_mma, cudaFuncAttributeMaxDynamicSharedMemorySize, G_SMEM);
    cudaFuncSetAttribute(attn_mma,     cudaFuncAttributeMaxDynamicSharedMemorySize, A_SMEM);

    x16_prep<<<(NT * DIMV) / (256 * 8), 256>>>(x);
    wt_prep<<<dim3(N3 / 32, DIMV / 32), 256>>>(w);
    qkv_gemm_mma<<<dim3(N3 / 128, NT / 128), 256, G_SMEM>>>(cosb, sinb, bq);
    attn_mma<<<dim3(SEQ / 128, BHN), 256, A_SMEM>>>((float*)d_out);
}